// round 12
// baseline (speedup 1.0000x reference)
#include <cuda_runtime.h>
#include <cuda_bf16.h>
#include <cstdint>

#define BB 32768
#define TT 78
#define HH 27
#define GG 108
#define CH 8
#define NCH 10    // ceil(78/8); last chunk has 6 steps

static __device__ float g_hbuf[(size_t)BB * TT * HH];   // inter-layer h (in-place per layer)

__device__ __forceinline__ float sigf(float x) {
    return __fdividef(1.0f, 1.0f + __expf(-x));
}
__device__ __forceinline__ float tapx(float x) {
    float r;
    asm("tanh.approx.f32 %0, %1;" : "=f"(r) : "f"(x));
    return r;
}
__device__ __forceinline__ float sig_apx(float x) {
    return fmaf(0.5f, tapx(0.5f * x), 0.5f);
}

typedef unsigned long long ull;
__device__ __forceinline__ ull pack2(float lo, float hi) {
    ull r;
    asm("mov.b64 %0, {%1, %2};" : "=l"(r) : "f"(lo), "f"(hi));
    return r;
}
__device__ __forceinline__ void unpack2(ull v, float& lo, float& hi) {
    asm("mov.b64 {%0, %1}, %2;" : "=f"(lo), "=f"(hi) : "l"(v));
}
__device__ __forceinline__ ull fma2(ull a, ull b, ull c) {
    ull d;
    asm("fma.rn.f32x2 %0, %1, %2, %3;" : "=l"(d) : "l"(a), "l"(b), "l"(c));
    return d;
}
__device__ __forceinline__ ull add2(ull a, ull b) {
    ull d;
    asm("add.rn.f32x2 %0, %1, %2;" : "=l"(d) : "l"(a), "l"(b));
    return d;
}
__device__ __forceinline__ uint32_t smem_u32(const void* p) {
    uint32_t a;
    asm("{ .reg .u64 t; cvta.to.shared.u64 t, %1; cvt.u32.u64 %0, t; }" : "=r"(a) : "l"(p));
    return a;
}

#define MMA16816(C, A, B)                                                     \
    asm volatile(                                                             \
        "mma.sync.aligned.m16n8k16.row.col.f32.bf16.bf16.f32 "                \
        "{%0,%1,%2,%3},{%4,%5,%6,%7},{%8,%9},{%0,%1,%2,%3};"                  \
        : "+f"((C)[0]), "+f"((C)[1]), "+f"((C)[2]), "+f"((C)[3])              \
        : "r"((A)[0]), "r"((A)[1]), "r"((A)[2]), "r"((A)[3]),                 \
          "r"((B)[0]), "r"((B)[1]))

// ---- SMEM layout (dynamic; 16B-aligned offsets) ----
#define SM_AS    0          // ushort[128*64]            16384
#define SM_XG    16384      // float4[128*29]            59392
#define SM_WHH   75776      // float[108*27]             11664
#define SM_HS2   87440      // ull  [16][2][32]           8192
#define SM_HLIN  95632      // float[16][2][32]           4096
#define SM_WL4   99728      // float4[32*8]               4096
#define SM_BLS   103824     // float[32]                   128
#define SM_TOT   103952

// ================= Fused layer: FF(HMMA, xg in SMEM) + recurrence =================
// Block = 16 batch elems, 128 threads. Time chunks of 8: A build -> MMA -> rec.
// SRC: 0 = xin, 1 = g_hbuf.   DOLIN: apply final linear head to dout, else h -> g_hbuf.

template<int SRC, int DOLIN>
__global__ void __launch_bounds__(128, 2)
fused_layer(const float* __restrict__ xin,
            const float* __restrict__ Wih,
            const float* __restrict__ Whh,
            const float* __restrict__ bih,
            const float* __restrict__ bhh,
            const float* __restrict__ h0,
            const float* __restrict__ c0,
            const float* __restrict__ Wl,
            const float* __restrict__ bl,
            float* __restrict__ dout)
{
    extern __shared__ char sm[];
    unsigned short* As  = (unsigned short*)(sm + SM_AS);
    float4*         xgs = (float4*)(sm + SM_XG);          // [row][29] row = blocal*8+tl
    float*          whh = (float*)(sm + SM_WHH);
    ull*            hs2 = (ull*)(sm + SM_HS2);            // [(elem*2+p)*32 + lane]
    float*          hln = (float*)(sm + SM_HLIN);
    float4*         Wl4 = (float4*)(sm + SM_WL4);         // [r*8 + q]
    float*          bls = (float*)(sm + SM_BLS);

    const int tid = threadIdx.x;
    const int w  = tid >> 5;
    const int l  = tid & 31;
    const int lq = l >> 2;
    const int lr = l & 3;
    const bool act = (l < HH);
    const int jl = act ? l : 0;

    // stage Whh (coalesced)
    for (int i = tid; i < GG * HH; i += 128) whh[i] = Whh[i];
    // zero A pad cols (27-31 hi, 59-63 lo) once; chunk builds only touch k<27
    for (int pz = tid; pz < 128 * 10; pz += 128) {
        int r = pz / 10, ci = pz % 10;
        int col = (ci < 5) ? (27 + ci) : (54 + ci);
        uint32_t byt = (uint32_t)(r * 128 + col * 2) ^ (uint32_t)((r & 7) << 4);
        As[byt >> 1] = 0;
    }
    if (DOLIN) {
        for (int i = tid; i < 32 * 8; i += 128) {
            int r = i >> 3, q = i & 7;
            float4 v = make_float4(0.f, 0.f, 0.f, 0.f);
            if (r < HH && q < 7) {
                if (4 * q + 0 < HH) v.x = Wl[r * HH + 4 * q + 0];
                if (4 * q + 1 < HH) v.y = Wl[r * HH + 4 * q + 1];
                if (4 * q + 2 < HH) v.z = Wl[r * HH + 4 * q + 2];
                if (4 * q + 3 < HH) v.w = Wl[r * HH + 4 * q + 3];
            }
            Wl4[i] = v;
        }
        if (tid < 32) bls[tid] = (tid < HH) ? bl[tid] : 0.f;
    }
    __syncthreads();

    // ---- rec weights in regs (gate pairs packed) ----
    ull wif[28], wgo[28];
#pragma unroll
    for (int k = 0; k < HH; ++k) {
        wif[k] = pack2(whh[(0 * HH + jl) * HH + k], whh[(1 * HH + jl) * HH + k]);
        wgo[k] = pack2(whh[(2 * HH + jl) * HH + k], whh[(3 * HH + jl) * HH + k]);
    }
    wif[27] = 0ull;
    wgo[27] = 0ull;
    const ull bif = pack2(bih[0 * HH + jl] + bhh[0 * HH + jl],
                          bih[1 * HH + jl] + bhh[1 * HH + jl]);
    const ull bgo = pack2(bih[2 * HH + jl] + bhh[2 * HH + jl],
                          bih[3 * HH + jl] + bhh[3 * HH + jl]);

    // ---- FF B fragments (round-11 verified): bf[hi/lo][khalf][ntile][reg] ----
    uint32_t bf[2][2][4][2];
#pragma unroll
    for (int kb = 0; kb < 2; ++kb)
#pragma unroll
    for (int nt = 0; nt < 4; ++nt)
#pragma unroll
    for (int r = 0; r < 2; ++r) {
        const int n = w * 32 + nt * 8 + lq;
        const int j = n >> 2, g = n & 3;
        const int k0 = kb * 16 + r * 8 + 2 * lr;
        float v0 = 0.f, v1 = 0.f;
        if (j < HH) {
            if (k0 < HH)     v0 = Wih[(g * HH + j) * HH + k0];
            if (k0 + 1 < HH) v1 = Wih[(g * HH + j) * HH + k0 + 1];
        }
        __nv_bfloat16 h0b = __float2bfloat16(v0);
        __nv_bfloat16 h1b = __float2bfloat16(v1);
        __nv_bfloat16 e0b = __float2bfloat16(v0 - __bfloat162float(h0b));
        __nv_bfloat16 e1b = __float2bfloat16(v1 - __bfloat162float(h1b));
        bf[0][kb][nt][r] = ((uint32_t)__bfloat16_as_ushort(h1b) << 16) |
                           (uint32_t)__bfloat16_as_ushort(h0b);
        bf[1][kb][nt][r] = ((uint32_t)__bfloat16_as_ushort(e1b) << 16) |
                           (uint32_t)__bfloat16_as_ushort(e0b);
    }

    // DOLIN: hoist linear weight row (t-invariant)
    float4 wlr[7];
    if (DOLIN) {
#pragma unroll
        for (int q = 0; q < 7; ++q) wlr[q] = Wl4[jl * 8 + q];
    }

    // ---- init state: warp w owns batch elems bbase + 4w .. 4w+3 ----
    const size_t bbase = (size_t)blockIdx.x * 16;
    float c_[4];
#pragma unroll
    for (int e = 0; e < 4; ++e) {
        size_t b = bbase + w * 4 + e;
        float hv = act ? h0[b * HH + l] : 0.f;
        float cv = act ? c0[b * HH + l] : 0.f;
        c_[e] = cv;
        hs2[((w * 4 + e) * 2 + 0) * 32 + l] = pack2(hv, hv);
        hs2[((w * 4 + e) * 2 + 1) * 32 + l] = 0ull;
        if (DOLIN) {
            hln[((w * 4 + e) * 2 + 0) * 32 + l] = hv;
            hln[((w * 4 + e) * 2 + 1) * 32 + l] = 0.f;
        }
    }
    __syncwarp();

    const float* in = SRC ? (const float*)g_hbuf : xin;
    const uint32_t smbA = smem_u32(As);

    int p = 0;
#pragma unroll 1
    for (int ch = 0; ch < NCH; ++ch) {
        const int T0 = ch * CH;
        const int steps = (T0 + CH <= TT) ? CH : (TT - T0);
        const int len = steps * HH;

        // ---- A build: 16 strips of `len` contiguous floats, hi/lo bf16, swizzled ----
        for (int i = tid; i < 16 * len; i += 128) {
            int bl_ = i / len, off = i - bl_ * len;
            float v = in[(bbase + bl_) * (size_t)(TT * HH) + (size_t)T0 * HH + off];
            int r = bl_ * 8 + off / HH, k = off % HH;
            __nv_bfloat16 hb = __float2bfloat16(v);
            __nv_bfloat16 eb = __float2bfloat16(v - __bfloat162float(hb));
            uint32_t x = (uint32_t)((r & 7) << 4);
            As[((uint32_t)(r * 128 + k * 2) ^ x) >> 1]        = __bfloat16_as_ushort(hb);
            As[((uint32_t)(r * 128 + (32 + k) * 2) ^ x) >> 1] = __bfloat16_as_ushort(eb);
        }
        __syncthreads();

        // ---- FF: HMMA -> xgs (SMEM) ----
#pragma unroll 1
        for (int mt = 0; mt < 8; ++mt) {
            const int row0 = mt * 16 + lq;
            const uint32_t xr = (uint32_t)((row0 & 7) << 4);

            uint32_t A0[4], A1[4], A2[4], A3[4];
            {
                const uint32_t rb0 = (uint32_t)(row0 * 128);
                const uint32_t rb1 = (uint32_t)((row0 + 8) * 128);
#pragma unroll
                for (int s = 0; s < 4; ++s) {
                    uint32_t* Af = (s == 0) ? A0 : (s == 1) ? A1 : (s == 2) ? A2 : A3;
                    const uint32_t cb = (uint32_t)(s * 32 + 4 * lr);
                    uint32_t a0 = smbA + ((rb0 + cb) ^ xr);
                    uint32_t a1 = smbA + ((rb1 + cb) ^ xr);
                    uint32_t a2 = smbA + ((rb0 + cb + 16) ^ xr);
                    uint32_t a3 = smbA + ((rb1 + cb + 16) ^ xr);
                    asm("ld.shared.b32 %0,[%1];" : "=r"(Af[0]) : "r"(a0));
                    asm("ld.shared.b32 %0,[%1];" : "=r"(Af[1]) : "r"(a1));
                    asm("ld.shared.b32 %0,[%1];" : "=r"(Af[2]) : "r"(a2));
                    asm("ld.shared.b32 %0,[%1];" : "=r"(Af[3]) : "r"(a3));
                }
            }

            float acc[4][4];
#pragma unroll
            for (int nt = 0; nt < 4; ++nt) {
                acc[nt][0] = acc[nt][1] = acc[nt][2] = acc[nt][3] = 0.f;
                MMA16816(acc[nt], A0, bf[0][0][nt]);
                MMA16816(acc[nt], A1, bf[0][1][nt]);
                MMA16816(acc[nt], A0, bf[1][0][nt]);
                MMA16816(acc[nt], A1, bf[1][1][nt]);
                MMA16816(acc[nt], A2, bf[0][0][nt]);
                MMA16816(acc[nt], A3, bf[0][1][nt]);
            }

#pragma unroll
            for (int nt = 0; nt < 4; ++nt) {
                const int j2 = 8 * w + 2 * nt + (lr >> 1);
                if (j2 < HH) {
                    const int gh = lr & 1;
                    float2* p0 = reinterpret_cast<float2*>(&xgs[row0 * 29 + j2]);
                    p0[gh] = make_float2(acc[nt][0], acc[nt][1]);
                    float2* p1 = reinterpret_cast<float2*>(&xgs[(row0 + 8) * 29 + j2]);
                    p1[gh] = make_float2(acc[nt][2], acc[nt][3]);
                }
            }
        }
        __syncthreads();

        // ---- REC: warp processes its 4 elems for `steps` timesteps ----
#pragma unroll 1
        for (int tl = 0; tl < steps; ++tl) {
            const int t = T0 + tl;

            ull aif[4], ago[4];
#pragma unroll
            for (int e = 0; e < 4; ++e) {
                int row = (w * 4 + e) * 8 + tl;
                float4 xv = act ? xgs[row * 29 + l] : make_float4(0.f, 0.f, 0.f, 0.f);
                aif[e] = add2(pack2(xv.x, xv.y), bif);
                ago[e] = add2(pack2(xv.z, xv.w), bgo);
            }

            const ulonglong2* hp0 = (const ulonglong2*)&hs2[((w * 4 + 0) * 2 + p) * 32];
            const ulonglong2* hp1 = (const ulonglong2*)&hs2[((w * 4 + 1) * 2 + p) * 32];
            const ulonglong2* hp2 = (const ulonglong2*)&hs2[((w * 4 + 2) * 2 + p) * 32];
            const ulonglong2* hp3 = (const ulonglong2*)&hs2[((w * 4 + 3) * 2 + p) * 32];
#pragma unroll
            for (int q = 0; q < 14; ++q) {
                ulonglong2 h20 = hp0[q], h21 = hp1[q], h22 = hp2[q], h23 = hp3[q];
                aif[0] = fma2(h20.x, wif[2 * q], aif[0]);
                ago[0] = fma2(h20.x, wgo[2 * q], ago[0]);
                aif[1] = fma2(h21.x, wif[2 * q], aif[1]);
                ago[1] = fma2(h21.x, wgo[2 * q], ago[1]);
                aif[2] = fma2(h22.x, wif[2 * q], aif[2]);
                ago[2] = fma2(h22.x, wgo[2 * q], ago[2]);
                aif[3] = fma2(h23.x, wif[2 * q], aif[3]);
                ago[3] = fma2(h23.x, wgo[2 * q], ago[3]);
                aif[0] = fma2(h20.y, wif[2 * q + 1], aif[0]);
                ago[0] = fma2(h20.y, wgo[2 * q + 1], ago[0]);
                aif[1] = fma2(h21.y, wif[2 * q + 1], aif[1]);
                ago[1] = fma2(h21.y, wgo[2 * q + 1], ago[1]);
                aif[2] = fma2(h22.y, wif[2 * q + 1], aif[2]);
                ago[2] = fma2(h22.y, wgo[2 * q + 1], ago[2]);
                aif[3] = fma2(h23.y, wif[2 * q + 1], aif[3]);
                ago[3] = fma2(h23.y, wgo[2 * q + 1], ago[3]);
            }

            float hn[4];
#pragma unroll
            for (int e = 0; e < 4; ++e) {
                float ai, af, ag, ao;
                unpack2(aif[e], ai, af);
                unpack2(ago[e], ag, ao);
                float gi = sig_apx(ai), gf = sigf(af), gg = tapx(ag), go = sig_apx(ao);
                c_[e] = fmaf(gf, c_[e], gi * gg);
                hn[e] = go * tapx(c_[e]);
                if (act) {
                    hs2[((w * 4 + e) * 2 + (p ^ 1)) * 32 + l] = pack2(hn[e], hn[e]);
                    if (DOLIN) hln[((w * 4 + e) * 2 + (p ^ 1)) * 32 + l] = hn[e];
                }
            }
            __syncwarp();

            if (DOLIN) {
#pragma unroll
                for (int e = 0; e < 4; ++e) {
                    const float4* hq = (const float4*)&hln[((w * 4 + e) * 2 + (p ^ 1)) * 32];
                    float l0 = bls[jl], l1 = 0.f;
#pragma unroll
                    for (int q = 0; q < 7; ++q) {
                        float4 h4 = hq[q];
                        float4 wl = wlr[q];
                        l0 = fmaf(wl.x, h4.x, l0);
                        l1 = fmaf(wl.y, h4.y, l1);
                        l0 = fmaf(wl.z, h4.z, l0);
                        l1 = fmaf(wl.w, h4.w, l1);
                    }
                    if (act)
                        dout[(bbase + w * 4 + e) * (size_t)(TT * HH) + (size_t)t * HH + l] =
                            l0 + l1;
                }
            } else {
#pragma unroll
                for (int e = 0; e < 4; ++e)
                    if (act)
                        g_hbuf[(bbase + w * 4 + e) * (size_t)(TT * HH) + (size_t)t * HH + l] =
                            hn[e];
            }
            p ^= 1;
        }
        __syncthreads();   // xgs free before next chunk's FF writes
    }
}

// ================= host =================
extern "C" void kernel_launch(void* const* d_in, const int* in_sizes, int n_in,
                              void* d_out, int out_size)
{
    const float* x   = (const float*)d_in[0];
    const float* h0  = (const float*)d_in[1];
    const float* c0  = (const float*)d_in[2];
    const float* Wih = (const float*)d_in[3];
    const float* Whh = (const float*)d_in[4];
    const float* bih = (const float*)d_in[5];
    const float* bhh = (const float*)d_in[6];
    const float* Wl  = (const float*)d_in[7];
    const float* bl  = (const float*)d_in[8];
    float* out = (float*)d_out;

    const size_t st = (size_t)BB * HH;
    const size_t wS = (size_t)GG * HH;
    const size_t bS = (size_t)GG;

    // opt-in to >48KB dynamic SMEM (idempotent host calls; not stream ops)
    cudaFuncSetAttribute(fused_layer<0, 0>, cudaFuncAttributeMaxDynamicSharedMemorySize, SM_TOT);
    cudaFuncSetAttribute(fused_layer<1, 0>, cudaFuncAttributeMaxDynamicSharedMemorySize, SM_TOT);
    cudaFuncSetAttribute(fused_layer<1, 1>, cudaFuncAttributeMaxDynamicSharedMemorySize, SM_TOT);

    const int grid = BB / 16;   // 2048

    // Layer 0: x -> h (g_hbuf)
    fused_layer<0, 0><<<grid, 128, SM_TOT>>>(x, Wih, Whh, bih, bhh,
                                             h0, c0, Wl, bl, out);
    // Layer 1: g_hbuf -> g_hbuf (in-place safe per-block)
    fused_layer<1, 0><<<grid, 128, SM_TOT>>>(x, Wih + wS, Whh + wS,
                                             bih + bS, bhh + bS,
                                             h0 + st, c0 + st, Wl, bl, out);
    // Layer 2: g_hbuf -> dout (fused linear head)
    fused_layer<1, 1><<<grid, 128, SM_TOT>>>(x, Wih + 2 * wS, Whh + 2 * wS,
                                             bih + 2 * bS, bhh + 2 * bS,
                                             h0 + 2 * st, c0 + 2 * st, Wl, bl, out);
}

// round 13
// speedup vs baseline: 1.4531x; 1.4531x over previous
#include <cuda_runtime.h>
#include <cuda_bf16.h>
#include <cuda_fp16.h>
#include <cstdint>

#define BB 32768
#define TT 78
#define HH 27
#define GG 108                 // 4*H
#define NT ((BB * TT) / 128)   // 19968 tiles of 128 rows

// Scratch (device globals; accessed ONLY from device code)
// xg element: uint2 = { half2(i,f), half2(g,o) }  -- 8 bytes (was float4)
static __device__ uint2 g_xg[(size_t)BB * TT * HH];
static __device__ float g_hbuf[(size_t)BB * TT * HH];   // inter-layer h

__device__ __forceinline__ float sigf(float x) {
    return __fdividef(1.0f, 1.0f + __expf(-x));
}
__device__ __forceinline__ float tapx(float x) {
    float r;
    asm("tanh.approx.f32 %0, %1;" : "=f"(r) : "f"(x));
    return r;
}
__device__ __forceinline__ float sig_apx(float x) {
    return fmaf(0.5f, tapx(0.5f * x), 0.5f);
}

typedef unsigned long long ull;
__device__ __forceinline__ ull pack2(float lo, float hi) {
    ull r;
    asm("mov.b64 %0, {%1, %2};" : "=l"(r) : "f"(lo), "f"(hi));
    return r;
}
__device__ __forceinline__ void unpack2(ull v, float& lo, float& hi) {
    asm("mov.b64 {%0, %1}, %2;" : "=f"(lo), "=f"(hi) : "l"(v));
}
__device__ __forceinline__ ull fma2(ull a, ull b, ull c) {
    ull d;
    asm("fma.rn.f32x2 %0, %1, %2, %3;" : "=l"(d) : "l"(a), "l"(b), "l"(c));
    return d;
}
__device__ __forceinline__ ull add2(ull a, ull b) {
    ull d;
    asm("add.rn.f32x2 %0, %1, %2;" : "=l"(d) : "l"(a), "l"(b));
    return d;
}

__device__ __forceinline__ void cpasync8(unsigned int saddr, const void* gaddr) {
    asm volatile("cp.async.ca.shared.global [%0], [%1], 8;" :: "r"(saddr), "l"(gaddr));
}
__device__ __forceinline__ void cpcommit() {
    asm volatile("cp.async.commit_group;" ::: "memory");
}
__device__ __forceinline__ void cpwait3() {
    asm volatile("cp.async.wait_group 3;" ::: "memory");
}
__device__ __forceinline__ uint32_t smem_u32(const void* p) {
    uint32_t a;
    asm("{ .reg .u64 t; cvta.to.shared.u64 t, %1; cvt.u32.u64 %0, t; }" : "=r"(a) : "l"(p));
    return a;
}

#define MMA16816(C, A, B)                                                     \
    asm volatile(                                                             \
        "mma.sync.aligned.m16n8k16.row.col.f32.bf16.bf16.f32 "                \
        "{%0,%1,%2,%3},{%4,%5,%6,%7},{%8,%9},{%0,%1,%2,%3};"                  \
        : "+f"((C)[0]), "+f"((C)[1]), "+f"((C)[2]), "+f"((C)[3])              \
        : "r"((A)[0]), "r"((A)[1]), "r"((A)[2]), "r"((A)[3]),                 \
          "r"((B)[0]), "r"((B)[1]))

// ================= MMA feed-forward: xg = in @ Wih^T (bf16 hi/lo split, fp32 acc,
// fp16 output). Warp w owns gate-interleaved cols n = 4j+g in [32w, 32w+32).

__global__ void __launch_bounds__(128, 4)
mmaFF_kernel(const float* __restrict__ xin,
             const float* __restrict__ Wih,
             int src)                        // 0: xin, 1: g_hbuf
{
    __shared__ __align__(16) unsigned short As[128 * 64];   // 16KB: cols 0-31 hi, 32-63 lo

    const int tid = threadIdx.x;
    const int w  = tid >> 5;
    const int l  = tid & 31;
    const int lq = l >> 2;
    const int lr = l & 3;

    // B fragments, register-stationary: bf[hi/lo][khalf][ntile][reg]
    uint32_t bf[2][2][4][2];
#pragma unroll
    for (int kb = 0; kb < 2; ++kb)
#pragma unroll
    for (int nt = 0; nt < 4; ++nt)
#pragma unroll
    for (int r = 0; r < 2; ++r) {
        const int n = w * 32 + nt * 8 + lq;
        const int j = n >> 2, g = n & 3;
        const int k0 = kb * 16 + r * 8 + 2 * lr;
        float v0 = 0.f, v1 = 0.f;
        if (j < HH) {
            if (k0 < HH)     v0 = Wih[(g * HH + j) * HH + k0];
            if (k0 + 1 < HH) v1 = Wih[(g * HH + j) * HH + k0 + 1];
        }
        __nv_bfloat16 h0 = __float2bfloat16(v0);
        __nv_bfloat16 h1 = __float2bfloat16(v1);
        __nv_bfloat16 e0 = __float2bfloat16(v0 - __bfloat162float(h0));
        __nv_bfloat16 e1 = __float2bfloat16(v1 - __bfloat162float(h1));
        bf[0][kb][nt][r] = ((uint32_t)__bfloat16_as_ushort(h1) << 16) |
                           (uint32_t)__bfloat16_as_ushort(h0);
        bf[1][kb][nt][r] = ((uint32_t)__bfloat16_as_ushort(e1) << 16) |
                           (uint32_t)__bfloat16_as_ushort(e0);
    }

    const float* inb = src ? (const float*)g_hbuf : xin;
    const size_t tile = blockIdx.x;
    const float* rs = inb + tile * (size_t)(128 * HH);

    // A build: zero pads then hi/lo split, XOR-swizzled
    for (int p = tid; p < 128 * 10; p += 128) {
        int r = p / 10, ci = p % 10;
        int col = (ci < 5) ? (27 + ci) : (54 + ci);
        uint32_t byt = (uint32_t)(r * 128 + col * 2) ^ (uint32_t)((r & 7) << 4);
        As[byt >> 1] = 0;
    }
    for (int i = tid; i < 128 * HH; i += 128) {
        int r = i / HH, k = i - r * HH;
        float v = rs[i];
        __nv_bfloat16 h = __float2bfloat16(v);
        __nv_bfloat16 e = __float2bfloat16(v - __bfloat162float(h));
        uint32_t x = (uint32_t)((r & 7) << 4);
        As[((uint32_t)(r * 128 + k * 2) ^ x) >> 1]        = __bfloat16_as_ushort(h);
        As[((uint32_t)(r * 128 + (32 + k) * 2) ^ x) >> 1] = __bfloat16_as_ushort(e);
    }
    __syncthreads();

    const uint32_t smbA = smem_u32(As);
    uint2* xg = g_xg + tile * (size_t)(128 * HH);

#pragma unroll 1
    for (int mt = 0; mt < 8; ++mt) {
        const int row0 = mt * 16 + lq;
        const uint32_t xr = (uint32_t)((row0 & 7) << 4);

        uint32_t A0[4], A1[4], A2[4], A3[4];
        {
            const uint32_t rb0 = (uint32_t)(row0 * 128);
            const uint32_t rb1 = (uint32_t)((row0 + 8) * 128);
#pragma unroll
            for (int s = 0; s < 4; ++s) {
                uint32_t* Af = (s == 0) ? A0 : (s == 1) ? A1 : (s == 2) ? A2 : A3;
                const uint32_t cb = (uint32_t)(s * 32 + 4 * lr);
                uint32_t a0 = smbA + ((rb0 + cb) ^ xr);
                uint32_t a1 = smbA + ((rb1 + cb) ^ xr);
                uint32_t a2 = smbA + ((rb0 + cb + 16) ^ xr);
                uint32_t a3 = smbA + ((rb1 + cb + 16) ^ xr);
                asm("ld.shared.b32 %0,[%1];" : "=r"(Af[0]) : "r"(a0));
                asm("ld.shared.b32 %0,[%1];" : "=r"(Af[1]) : "r"(a1));
                asm("ld.shared.b32 %0,[%1];" : "=r"(Af[2]) : "r"(a2));
                asm("ld.shared.b32 %0,[%1];" : "=r"(Af[3]) : "r"(a3));
            }
        }

        float acc[4][4];
#pragma unroll
        for (int nt = 0; nt < 4; ++nt) {
            acc[nt][0] = acc[nt][1] = acc[nt][2] = acc[nt][3] = 0.f;
            MMA16816(acc[nt], A0, bf[0][0][nt]);
            MMA16816(acc[nt], A1, bf[0][1][nt]);
            MMA16816(acc[nt], A0, bf[1][0][nt]);
            MMA16816(acc[nt], A1, bf[1][1][nt]);
            MMA16816(acc[nt], A2, bf[0][0][nt]);
            MMA16816(acc[nt], A3, bf[0][1][nt]);
        }

        // C -> g_xg (fp16): lane fragment = half2 of gate pair (i,f) or (g,o)
#pragma unroll
        for (int nt = 0; nt < 4; ++nt) {
            const int jj = 8 * w + 2 * nt + (lr >> 1);
            if (jj < HH) {
                const int gh = lr & 1;   // 0: .x = half2(i,f) ; 1: .y = half2(g,o)
                __half2 v0 = __float22half2_rn(make_float2(acc[nt][0], acc[nt][1]));
                __half2 v1 = __float22half2_rn(make_float2(acc[nt][2], acc[nt][3]));
                uint32_t* p0 = reinterpret_cast<uint32_t*>(&xg[(size_t)row0 * HH + jj]);
                p0[gh] = *reinterpret_cast<uint32_t*>(&v0);
                uint32_t* p1 = reinterpret_cast<uint32_t*>(&xg[(size_t)(row0 + 8) * HH + jj]);
                p1[gh] = *reinterpret_cast<uint32_t*>(&v1);
            }
        }
    }
}

// ================= Recurrence (2 batch elems/warp; bias folded here) ==================

template<bool DOLIN>
__global__ void __launch_bounds__(128, 3)
phaseB_kernel(const float* __restrict__ h0,
              const float* __restrict__ c0,
              const float* __restrict__ Whh,
              const float* __restrict__ bih,
              const float* __restrict__ bhh,
              const float* __restrict__ Wl,
              const float* __restrict__ bl,
              float* __restrict__ dout)
{
    __shared__ alignas(16) ull hs2[4][2][2][32];
    __shared__ float whh_s[GG * HH];
    __shared__ alignas(16) uint2 xstage[4][4][2][32];     // 8B/elem -> 8KB total
    __shared__ alignas(16) float hs_lin[4][2][2][32];
    __shared__ alignas(16) float4 Wl4[32][8];
    __shared__ float bls[32];

    const int tid = threadIdx.x;
    const int w   = tid >> 5;
    const int j   = tid & 31;
    const bool act = (j < HH);
    const int jj = act ? j : 0;

    for (int i = tid; i < GG * HH; i += 128) whh_s[i] = Whh[i];
    if (DOLIN) {
        for (int i = tid; i < 32 * 7; i += 128) {
            int r = i / 7, q = i % 7;
            float4 v;
            v.x = (r < HH && 4 * q + 0 < HH) ? Wl[r * HH + 4 * q + 0] : 0.f;
            v.y = (r < HH && 4 * q + 1 < HH) ? Wl[r * HH + 4 * q + 1] : 0.f;
            v.z = (r < HH && 4 * q + 2 < HH) ? Wl[r * HH + 4 * q + 2] : 0.f;
            v.w = (r < HH && 4 * q + 3 < HH) ? Wl[r * HH + 4 * q + 3] : 0.f;
            Wl4[r][q] = v;
        }
        if (tid < 32) bls[tid] = (tid < HH) ? bl[tid] : 0.f;
    }
    __syncthreads();

    ull wif[28], wgo[28];
#pragma unroll
    for (int k = 0; k < HH; ++k) {
        wif[k] = pack2(whh_s[(0 * HH + jj) * HH + k], whh_s[(1 * HH + jj) * HH + k]);
        wgo[k] = pack2(whh_s[(2 * HH + jj) * HH + k], whh_s[(3 * HH + jj) * HH + k]);
    }
    wif[27] = 0ull;
    wgo[27] = 0ull;
    const ull bif = pack2(bih[0 * HH + jj] + bhh[0 * HH + jj],
                          bih[1 * HH + jj] + bhh[1 * HH + jj]);
    const ull bgo = pack2(bih[2 * HH + jj] + bhh[2 * HH + jj],
                          bih[3 * HH + jj] + bhh[3 * HH + jj]);

    const size_t b0 = (size_t)blockIdx.x * 8 + w * 2;
    const size_t b1 = b0 + 1;

    float cA = act ? c0[b0 * HH + j] : 0.f;
    float cB = act ? c0[b1 * HH + j] : 0.f;
    float hA = act ? h0[b0 * HH + j] : 0.f;
    float hB = act ? h0[b1 * HH + j] : 0.f;
    hs2[w][0][0][j] = pack2(hA, hA);
    hs2[w][1][0][j] = pack2(hB, hB);
    if (DOLIN) { hs_lin[w][0][0][j] = hA; hs_lin[w][1][0][j] = hB; }
    __syncwarp();

    const uint2* xp0 = g_xg + b0 * (size_t)(TT * HH);
    const uint2* xp1 = g_xg + b1 * (size_t)(TT * HH);
    float* op0 = (DOLIN ? dout : g_hbuf) + b0 * (size_t)(TT * HH);
    float* op1 = (DOLIN ? dout : g_hbuf) + b1 * (size_t)(TT * HH);

    // ring: stage stride = 4w*2e*32l*8B = 2048B ; elem stride = 256B
    const unsigned int xsbase =
        (unsigned int)__cvta_generic_to_shared(&xstage[0][w][0][j]);

#pragma unroll
    for (int s = 0; s < 3; ++s) {
        if (act) {
            cpasync8(xsbase + (unsigned)s * 2048u,        xp0 + s * HH + j);
            cpasync8(xsbase + (unsigned)s * 2048u + 256u, xp1 + s * HH + j);
        }
        cpcommit();
    }

    int p = 0;
    for (int t = 0; t < TT; ++t) {
        if (t + 3 < TT && act) {
            unsigned int sa = xsbase + (unsigned)((t + 3) & 3) * 2048u;
            cpasync8(sa,        xp0 + (t + 3) * HH + j);
            cpasync8(sa + 256u, xp1 + (t + 3) * HH + j);
        }
        cpcommit();
        cpwait3();
        uint2 xrA = xstage[t & 3][w][0][j];
        uint2 xrB = xstage[t & 3][w][1][j];
        float2 fifA = __half22float2(*reinterpret_cast<__half2*>(&xrA.x));
        float2 fgoA = __half22float2(*reinterpret_cast<__half2*>(&xrA.y));
        float2 fifB = __half22float2(*reinterpret_cast<__half2*>(&xrB.x));
        float2 fgoB = __half22float2(*reinterpret_cast<__half2*>(&xrB.y));

        const ulonglong2* hpA = reinterpret_cast<const ulonglong2*>(&hs2[w][0][p][0]);
        const ulonglong2* hpB = reinterpret_cast<const ulonglong2*>(&hs2[w][1][p][0]);

        ull aifA = add2(pack2(fifA.x, fifA.y), bif);
        ull agoA = add2(pack2(fgoA.x, fgoA.y), bgo);
        ull aifB = add2(pack2(fifB.x, fifB.y), bif);
        ull agoB = add2(pack2(fgoB.x, fgoB.y), bgo);
#pragma unroll
        for (int q = 0; q < 14; ++q) {
            ulonglong2 h2A = hpA[q];
            ulonglong2 h2B = hpB[q];
            aifA = fma2(h2A.x, wif[2 * q],     aifA);
            agoA = fma2(h2A.x, wgo[2 * q],     agoA);
            aifB = fma2(h2B.x, wif[2 * q],     aifB);
            agoB = fma2(h2B.x, wgo[2 * q],     agoB);
            aifA = fma2(h2A.y, wif[2 * q + 1], aifA);
            agoA = fma2(h2A.y, wgo[2 * q + 1], agoA);
            aifB = fma2(h2B.y, wif[2 * q + 1], aifB);
            agoB = fma2(h2B.y, wgo[2 * q + 1], agoB);
        }

        float ai, af, ag, ao;
        unpack2(aifA, ai, af);
        unpack2(agoA, ag, ao);
        float giA = sig_apx(ai), gfA = sigf(af), ggA = tapx(ag), goA = sig_apx(ao);
        cA = fmaf(gfA, cA, giA * ggA);
        float hnA = goA * tapx(cA);

        unpack2(aifB, ai, af);
        unpack2(agoB, ag, ao);
        float giB = sig_apx(ai), gfB = sigf(af), ggB = tapx(ag), goB = sig_apx(ao);
        cB = fmaf(gfB, cB, giB * ggB);
        float hnB = goB * tapx(cB);

        if (act) {
            hs2[w][0][p ^ 1][j] = pack2(hnA, hnA);
            hs2[w][1][p ^ 1][j] = pack2(hnB, hnB);
            if (DOLIN) {
                hs_lin[w][0][p ^ 1][j] = hnA;
                hs_lin[w][1][p ^ 1][j] = hnB;
            }
        }
        __syncwarp();

        if (DOLIN) {
            const float4* hqA = reinterpret_cast<const float4*>(&hs_lin[w][0][p ^ 1][0]);
            const float4* hqB = reinterpret_cast<const float4*>(&hs_lin[w][1][p ^ 1][0]);
            float lA0 = bls[jj], lA1 = 0.f, lB0 = bls[jj], lB1 = 0.f;
#pragma unroll
            for (int q = 0; q < 7; ++q) {
                float4 h4A = hqA[q];
                float4 h4B = hqB[q];
                float4 wl = Wl4[jj][q];
                lA0 = fmaf(wl.x, h4A.x, lA0);
                lA1 = fmaf(wl.y, h4A.y, lA1);
                lA0 = fmaf(wl.z, h4A.z, lA0);
                lA1 = fmaf(wl.w, h4A.w, lA1);
                lB0 = fmaf(wl.x, h4B.x, lB0);
                lB1 = fmaf(wl.y, h4B.y, lB1);
                lB0 = fmaf(wl.z, h4B.z, lB0);
                lB1 = fmaf(wl.w, h4B.w, lB1);
            }
            if (act) {
                op0[t * HH + j] = lA0 + lA1;
                op1[t * HH + j] = lB0 + lB1;
            }
        } else {
            if (act) {
                op0[t * HH + j] = hnA;
                op1[t * HH + j] = hnB;
            }
        }

        p ^= 1;
    }
}

// ================= host =================
extern "C" void kernel_launch(void* const* d_in, const int* in_sizes, int n_in,
                              void* d_out, int out_size)
{
    const float* x   = (const float*)d_in[0];
    const float* h0  = (const float*)d_in[1];
    const float* c0  = (const float*)d_in[2];
    const float* Wih = (const float*)d_in[3];
    const float* Whh = (const float*)d_in[4];
    const float* bih = (const float*)d_in[5];
    const float* bhh = (const float*)d_in[6];
    const float* Wl  = (const float*)d_in[7];
    const float* bl  = (const float*)d_in[8];
    float* out = (float*)d_out;

    const size_t st = (size_t)BB * HH;
    const size_t wS = (size_t)GG * HH;
    const size_t bS = (size_t)GG;

    const int gridB = BB / 8;   // 4096

    // L0: FF (tensor) x -> xg ; rec -> hbuf
    mmaFF_kernel<<<NT, 128>>>(x, Wih, 0);
    phaseB_kernel<false><<<gridB, 128>>>(h0, c0, Whh, bih, bhh, Wl, bl, out);
    // L1: FF hbuf -> xg ; rec -> hbuf
    mmaFF_kernel<<<NT, 128>>>(x, Wih + wS, 1);
    phaseB_kernel<false><<<gridB, 128>>>(h0 + st, c0 + st, Whh + wS,
                                         bih + bS, bhh + bS, Wl, bl, out);
    // L2: FF hbuf -> xg ; rec + linear head -> out
    mmaFF_kernel<<<NT, 128>>>(x, Wih + 2 * wS, 1);
    phaseB_kernel<true><<<gridB, 128>>>(h0 + 2 * st, c0 + 2 * st, Whh + 2 * wS,
                                        bih + 2 * bS, bhh + 2 * bS, Wl, bl, out);
}

// round 14
// speedup vs baseline: 1.6628x; 1.1443x over previous
#include <cuda_runtime.h>
#include <cuda_bf16.h>
#include <cstdint>

#define BB 32768
#define TT 78
#define HH 27
#define T27 (TT * HH)    // 2106
#define GG 108

// h between layers, stored as (bf16hi<<16 | bf16lo) — exactly what MMA A-build needs
static __device__ unsigned int g_hbuf[(size_t)BB * TT * HH];

__device__ __forceinline__ float sigf(float x) {          // exact f-gate
    return __fdividef(1.f, 1.f + __expf(-x));
}
__device__ __forceinline__ float tapx(float x) {
    float r;
    asm("tanh.approx.f32 %0,%1;" : "=f"(r) : "f"(x));
    return r;
}
__device__ __forceinline__ float sig_apx(float x) {
    return fmaf(0.5f, tapx(0.5f * x), 0.5f);
}

__device__ __forceinline__ void cpa4(unsigned s, const void* g) {
    asm volatile("cp.async.ca.shared.global [%0],[%1],4;" :: "r"(s), "l"(g));
}
#define CPC() asm volatile("cp.async.commit_group;" ::: "memory")
#define CPW1() asm volatile("cp.async.wait_group 1;" ::: "memory")
#define CPW0() asm volatile("cp.async.wait_group 0;" ::: "memory")

__device__ __forceinline__ uint32_t su32(const void* p) {
    uint32_t a;
    asm("{.reg .u64 t; cvta.to.shared.u64 t,%1; cvt.u32.u64 %0,t;}" : "=r"(a) : "l"(p));
    return a;
}

#define MMA(C, A, B)                                                          \
    asm volatile(                                                             \
        "mma.sync.aligned.m16n8k16.row.col.f32.bf16.bf16.f32 "                \
        "{%0,%1,%2,%3},{%4,%5,%6,%7},{%8,%9},{%0,%1,%2,%3};"                  \
        : "+f"((C)[0]), "+f"((C)[1]), "+f"((C)[2]), "+f"((C)[3])              \
        : "r"((A)[0]), "r"((A)[1]), "r"((A)[2]), "r"((A)[3]),                 \
          "r"((B)[0]), "r"((B)[1]))

__device__ __forceinline__ void bsplit(float v, unsigned short& h, unsigned short& l) {
    __nv_bfloat16 hb = __float2bfloat16(v);
    __nv_bfloat16 lb = __float2bfloat16(v - __bfloat162float(hb));
    h = __bfloat16_as_ushort(hb);
    l = __bfloat16_as_ushort(lb);
}

// ---- rec SMEM map (dynamic, bytes) ----
// As tables: [p][hi/lo]: p*16384 + hl*8192, each 64 rows x 128B (64 bf16 cols)
// xring: 32768 + slot*6912 (64*27*4)
// h_sm:  46592 (64*27*4)   total 53504
#define SM_XR 32768
#define SM_HS 46592
#define SM_TOT 53504

// ================= Fused layer: per-t MMA of [h|x] @ [Whh|Wih]^T + LSTM cell ========
// Block = 64 batch rows. Warp w owns gate-interleaved n=4j+g, jj in [8w,8w+8).

template<int SRC>   // 0: xin fp32 ; 1: g_hbuf packed bf16
__global__ void __launch_bounds__(128, 3)
fused_rec(const float* __restrict__ xin,
          const float* __restrict__ Wih, const float* __restrict__ Whh,
          const float* __restrict__ bih, const float* __restrict__ bhh,
          const float* __restrict__ h0, const float* __restrict__ c0)
{
    extern __shared__ char sm[];
    const uint32_t smb = su32(sm);
    unsigned int* h_sm = (unsigned int*)(sm + SM_HS);

    const int tid = threadIdx.x, w = tid >> 5, l = tid & 31;
    const int lq = l >> 2, lr = l & 3, gh = lr & 1;
    const int ntmax = (w == 3) ? 2 : 4;      // jj>=28 slices are dead weight
    const size_t bbase = (size_t)blockIdx.x * 64;

    // zero all 4 A tables (pad cols 54-63 stay zero forever)
    for (int i = tid; i < 8192; i += 128) ((uint32_t*)sm)[i] = 0;

    // ---- B fragments: B[n][k] = k<27 ? Whh[g*27+j][k] : (k<54 ? Wih[g*27+j][k-27] : 0)
    uint32_t bfh[4][4][2], bfl[4][4][2];
#pragma unroll
    for (int kb = 0; kb < 4; ++kb)
#pragma unroll
    for (int nt = 0; nt < 4; ++nt)
#pragma unroll
    for (int r = 0; r < 2; ++r) {
        int n = w * 32 + nt * 8 + lq, j = n >> 2, g = n & 3;
        int k0 = kb * 16 + r * 8 + 2 * lr;
        float v0 = 0.f, v1 = 0.f;
        if (j < HH) {
            if (k0 < HH) v0 = Whh[(g * HH + j) * HH + k0];
            else if (k0 < 54) v0 = Wih[(g * HH + j) * HH + k0 - HH];
            int k1 = k0 + 1;
            if (k1 < HH) v1 = Whh[(g * HH + j) * HH + k1];
            else if (k1 < 54) v1 = Wih[(g * HH + j) * HH + k1 - HH];
        }
        unsigned short h0u, l0u, h1u, l1u;
        bsplit(v0, h0u, l0u);
        bsplit(v1, h1u, l1u);
        bfh[kb][nt][r] = ((uint32_t)h1u << 16) | h0u;
        bfl[kb][nt][r] = ((uint32_t)l1u << 16) | l0u;
    }

    // bias per nt (folded into acc init)
    float bias0[4], bias1[4];
#pragma unroll
    for (int nt = 0; nt < 4; ++nt) {
        int jj = w * 8 + 2 * nt + (lr >> 1);
        int g0 = 2 * gh;
        bias0[nt] = (jj < HH) ? bih[g0 * HH + jj] + bhh[g0 * HH + jj] : 0.f;
        bias1[nt] = (jj < HH) ? bih[(g0 + 1) * HH + jj] + bhh[(g0 + 1) * HH + jj] : 0.f;
    }

    // c registers: lane owns (row, jj) per (mt, nt)
    float cReg[16];
#pragma unroll
    for (int mt = 0; mt < 4; ++mt)
#pragma unroll
    for (int nt = 0; nt < 4; ++nt) {
        int jj = w * 8 + 2 * nt + (lr >> 1);
        int row = mt * 16 + lq + (gh ? 8 : 0);
        cReg[mt * 4 + nt] = (jj < HH) ? c0[(bbase + row) * HH + jj] : 0.f;
    }

    __syncthreads();   // zeros visible before anyone writes A tables

    // h0 -> As[0] cols 0..26 (thread-private mapping: lane=col, warp's 16 rows)
    if (l < HH) {
        for (int rr = 0; rr < 16; ++rr) {
            int row = w * 16 + rr;
            unsigned short hu, lu;
            bsplit(h0[(bbase + row) * HH + l], hu, lu);
            uint32_t a = ((uint32_t)(row * 128 + l * 2)) ^ (uint32_t)((row & 7) << 4);
            ((unsigned short*)sm)[a >> 1] = hu;
            ((unsigned short*)(sm + 8192))[a >> 1] = lu;
        }
    }

    const char* src = SRC ? (const char*)g_hbuf : (const char*)xin;

    // prologue: cp.async x0 -> slot0, x1 -> slot1 (self-consistent thread mapping)
#pragma unroll
    for (int t0 = 0; t0 < 2; ++t0) {
        if (l < HH) {
            for (int rr = 0; rr < 16; ++rr) {
                int row = w * 16 + rr;
                cpa4(smb + SM_XR + t0 * 6912 + (uint32_t)(row * HH + l) * 4,
                     src + ((bbase + row) * T27 + (size_t)t0 * HH + l) * 4);
            }
        }
        CPC();
    }
    CPW0();
    // convert x0 -> As[0] cols 27..53
    if (l < HH) {
        for (int rr = 0; rr < 16; ++rr) {
            int row = w * 16 + rr;
            unsigned short hu, lu;
            if (SRC == 0) {
                bsplit(((const float*)(sm + SM_XR))[row * HH + l], hu, lu);
            } else {
                unsigned int u = ((const unsigned int*)(sm + SM_XR))[row * HH + l];
                hu = (unsigned short)(u >> 16);
                lu = (unsigned short)(u & 0xffffu);
            }
            uint32_t a = ((uint32_t)(row * 128 + (HH + l) * 2)) ^ (uint32_t)((row & 7) << 4);
            ((unsigned short*)sm)[a >> 1] = hu;
            ((unsigned short*)(sm + 8192))[a >> 1] = lu;
        }
    }
    __syncthreads();

    int p = 0;
#pragma unroll 1
    for (int t = 0; t < TT; ++t) {
        // issue x_{t+2} -> ring[t&1]
        if (t + 2 < TT && l < HH) {
            for (int rr = 0; rr < 16; ++rr) {
                int row = w * 16 + rr;
                cpa4(smb + SM_XR + (t & 1) * 6912 + (uint32_t)(row * HH + l) * 4,
                     src + ((bbase + row) * T27 + (size_t)(t + 2) * HH + l) * 4);
            }
        }
        CPC();
        CPW1();   // x_{t+1} landed (this thread's own transfers)

        // convert x_{t+1} -> As[p^1] cols 27..53
        if (t + 1 < TT && l < HH) {
            char* hiB = sm + (p ^ 1) * 16384;
            char* loB = hiB + 8192;
            const char* slot = sm + SM_XR + ((t + 1) & 1) * 6912;
            for (int rr = 0; rr < 16; ++rr) {
                int row = w * 16 + rr;
                unsigned short hu, lu;
                if (SRC == 0) {
                    bsplit(((const float*)slot)[row * HH + l], hu, lu);
                } else {
                    unsigned int u = ((const unsigned int*)slot)[row * HH + l];
                    hu = (unsigned short)(u >> 16);
                    lu = (unsigned short)(u & 0xffffu);
                }
                uint32_t a = ((uint32_t)(row * 128 + (HH + l) * 2)) ^
                             (uint32_t)((row & 7) << 4);
                ((unsigned short*)hiB)[a >> 1] = hu;
                ((unsigned short*)loB)[a >> 1] = lu;
            }
        }

        const uint32_t hiBase = smb + p * 16384;
        const uint32_t loBase = hiBase + 8192;
        char* hiW = sm + (p ^ 1) * 16384;
        char* loW = hiW + 8192;

#pragma unroll
        for (int mt = 0; mt < 4; ++mt) {
            const int row0 = mt * 16 + lq;
            const uint32_t xr = (uint32_t)((row0 & 7) << 4);
            const uint32_t rb0 = (uint32_t)(row0 * 128);
            const uint32_t rb1 = (uint32_t)((row0 + 8) * 128);
            uint32_t Ah[4][4], Al[4][4];
#pragma unroll
            for (int s = 0; s < 4; ++s) {
                uint32_t cb = (uint32_t)(s * 32 + 4 * lr);
                asm("ld.shared.b32 %0,[%1];" : "=r"(Ah[s][0]) : "r"(hiBase + ((rb0 + cb) ^ xr)));
                asm("ld.shared.b32 %0,[%1];" : "=r"(Ah[s][1]) : "r"(hiBase + ((rb1 + cb) ^ xr)));
                asm("ld.shared.b32 %0,[%1];" : "=r"(Ah[s][2]) : "r"(hiBase + ((rb0 + cb + 16) ^ xr)));
                asm("ld.shared.b32 %0,[%1];" : "=r"(Ah[s][3]) : "r"(hiBase + ((rb1 + cb + 16) ^ xr)));
                asm("ld.shared.b32 %0,[%1];" : "=r"(Al[s][0]) : "r"(loBase + ((rb0 + cb) ^ xr)));
                asm("ld.shared.b32 %0,[%1];" : "=r"(Al[s][1]) : "r"(loBase + ((rb1 + cb) ^ xr)));
                asm("ld.shared.b32 %0,[%1];" : "=r"(Al[s][2]) : "r"(loBase + ((rb0 + cb + 16) ^ xr)));
                asm("ld.shared.b32 %0,[%1];" : "=r"(Al[s][3]) : "r"(loBase + ((rb1 + cb + 16) ^ xr)));
            }
#pragma unroll
            for (int nt = 0; nt < 4; ++nt) {
                if (nt < ntmax) {
                    float acc[4] = {bias0[nt], bias1[nt], bias0[nt], bias1[nt]};
#pragma unroll
                    for (int s = 0; s < 4; ++s) MMA(acc, Ah[s], bfh[s][nt]);
#pragma unroll
                    for (int s = 0; s < 4; ++s) MMA(acc, Ah[s], bfl[s][nt]);
#pragma unroll
                    for (int s = 0; s < 4; ++s) MMA(acc, Al[s], bfh[s][nt]);

                    // gate exchange: partner lane (l^1) holds the other gate pair
                    float v0 = __shfl_xor_sync(0xffffffffu, acc[0], 1);
                    float v1 = __shfl_xor_sync(0xffffffffu, acc[1], 1);
                    float v2 = __shfl_xor_sync(0xffffffffu, acc[2], 1);
                    float v3 = __shfl_xor_sync(0xffffffffu, acc[3], 1);
                    int row;
                    float xi, xf, xg, xo;
                    if (gh == 0) { row = row0;     xi = acc[0]; xf = acc[1]; xg = v0; xo = v1; }
                    else         { row = row0 + 8; xi = v2; xf = v3; xg = acc[2]; xo = acc[3]; }
                    float gi = sig_apx(xi), gf = sigf(xf), gg = tapx(xg), go = sig_apx(xo);
                    float cc = fmaf(gf, cReg[mt * 4 + nt], gi * gg);
                    cReg[mt * 4 + nt] = cc;
                    float hv = go * tapx(cc);
                    int jj = w * 8 + 2 * nt + (lr >> 1);
                    if (jj < HH) {
                        unsigned short hu, lu;
                        bsplit(hv, hu, lu);
                        uint32_t a = ((uint32_t)(row * 128 + jj * 2)) ^
                                     (uint32_t)((row & 7) << 4);
                        ((unsigned short*)hiW)[a >> 1] = hu;
                        ((unsigned short*)loW)[a >> 1] = lu;
                        h_sm[row * HH + jj] = ((unsigned int)hu << 16) | lu;
                    }
                }
            }
        }
        __syncthreads();

        // flush h_t (packed bf16 pair) -> g_hbuf, coalesced
#pragma unroll 1
        for (int it = 0; it < 14; ++it) {
            int idx = it * 128 + tid;
            if (idx < 64 * HH) {
                int row = idx / HH, k = idx - row * HH;
                g_hbuf[(bbase + row) * T27 + (size_t)t * HH + k] = h_sm[idx];
            }
        }
        __syncthreads();
        p ^= 1;
    }
}

// ================= Final linear: dout = h @ Wl^T + bl (HMMA, hbuf is bf16 hi/lo) ====

__global__ void __launch_bounds__(128, 4)
lin_kernel(const float* __restrict__ Wl, const float* __restrict__ bl,
           float* __restrict__ dout)
{
    __shared__ __align__(16) unsigned short AsH[128 * 64];
    __shared__ __align__(16) unsigned short AsL[128 * 64];

    const int tid = threadIdx.x, w = tid >> 5, l = tid & 31;
    const int lq = l >> 2, lr = l & 3;

    for (int i = tid; i < 128 * 64; i += 128) { AsH[i] = 0; AsL[i] = 0; }

    // B frags: Wl[n][k], K pad 32
    uint32_t bfh[2][4][2], bfl[2][4][2];
#pragma unroll
    for (int kb = 0; kb < 2; ++kb)
#pragma unroll
    for (int nt = 0; nt < 4; ++nt)
#pragma unroll
    for (int r = 0; r < 2; ++r) {
        int n = nt * 8 + lq;
        int k0 = kb * 16 + r * 8 + 2 * lr;
        float v0 = (n < HH && k0 < HH) ? Wl[n * HH + k0] : 0.f;
        float v1 = (n < HH && k0 + 1 < HH) ? Wl[n * HH + k0 + 1] : 0.f;
        unsigned short h0u, l0u, h1u, l1u;
        bsplit(v0, h0u, l0u);
        bsplit(v1, h1u, l1u);
        bfh[kb][nt][r] = ((uint32_t)h1u << 16) | h0u;
        bfl[kb][nt][r] = ((uint32_t)l1u << 16) | l0u;
    }
    float2 bias[4];
#pragma unroll
    for (int nt = 0; nt < 4; ++nt) {
        int n0 = nt * 8 + 2 * lr;
        bias[nt].x = (n0 < HH) ? bl[n0] : 0.f;
        bias[nt].y = (n0 + 1 < HH) ? bl[n0 + 1] : 0.f;
    }
    __syncthreads();

    // A build: unpack hbuf (coalesced)
    const size_t tile = blockIdx.x;
    const unsigned int* hb = g_hbuf + tile * (size_t)(128 * HH);
    for (int i = tid; i < 128 * HH; i += 128) {
        unsigned int u = hb[i];
        int row = i / HH, k = i - row * HH;
        uint32_t a = ((uint32_t)(row * 128 + k * 2)) ^ (uint32_t)((row & 7) << 4);
        AsH[a >> 1] = (unsigned short)(u >> 16);
        AsL[a >> 1] = (unsigned short)(u & 0xffffu);
    }
    __syncthreads();

    const uint32_t hiB = su32(AsH), loB = su32(AsL);
#pragma unroll
    for (int mi = 0; mi < 2; ++mi) {
        const int mt = w * 2 + mi;
        const int row0 = mt * 16 + lq;
        const uint32_t xr = (uint32_t)((row0 & 7) << 4);
        const uint32_t rb0 = (uint32_t)(row0 * 128);
        const uint32_t rb1 = (uint32_t)((row0 + 8) * 128);
        uint32_t Ah[2][4], Al[2][4];
#pragma unroll
        for (int s = 0; s < 2; ++s) {
            uint32_t cb = (uint32_t)(s * 32 + 4 * lr);
            asm("ld.shared.b32 %0,[%1];" : "=r"(Ah[s][0]) : "r"(hiB + ((rb0 + cb) ^ xr)));
            asm("ld.shared.b32 %0,[%1];" : "=r"(Ah[s][1]) : "r"(hiB + ((rb1 + cb) ^ xr)));
            asm("ld.shared.b32 %0,[%1];" : "=r"(Ah[s][2]) : "r"(hiB + ((rb0 + cb + 16) ^ xr)));
            asm("ld.shared.b32 %0,[%1];" : "=r"(Ah[s][3]) : "r"(hiB + ((rb1 + cb + 16) ^ xr)));
            asm("ld.shared.b32 %0,[%1];" : "=r"(Al[s][0]) : "r"(loB + ((rb0 + cb) ^ xr)));
            asm("ld.shared.b32 %0,[%1];" : "=r"(Al[s][1]) : "r"(loB + ((rb1 + cb) ^ xr)));
            asm("ld.shared.b32 %0,[%1];" : "=r"(Al[s][2]) : "r"(loB + ((rb0 + cb + 16) ^ xr)));
            asm("ld.shared.b32 %0,[%1];" : "=r"(Al[s][3]) : "r"(loB + ((rb1 + cb + 16) ^ xr)));
        }
#pragma unroll
        for (int nt = 0; nt < 4; ++nt) {
            float acc[4] = {bias[nt].x, bias[nt].y, bias[nt].x, bias[nt].y};
#pragma unroll
            for (int s = 0; s < 2; ++s) MMA(acc, Ah[s], bfh[s][nt]);
#pragma unroll
            for (int s = 0; s < 2; ++s) MMA(acc, Ah[s], bfl[s][nt]);
#pragma unroll
            for (int s = 0; s < 2; ++s) MMA(acc, Al[s], bfh[s][nt]);
            int n0 = nt * 8 + 2 * lr;
            float* d0 = dout + (tile * 128 + row0) * (size_t)HH;
            float* d1 = dout + (tile * 128 + row0 + 8) * (size_t)HH;
            if (n0 < HH)     { d0[n0] = acc[0];     d1[n0] = acc[2]; }
            if (n0 + 1 < HH) { d0[n0 + 1] = acc[1]; d1[n0 + 1] = acc[3]; }
        }
    }
}

// ================= host =================
extern "C" void kernel_launch(void* const* d_in, const int* in_sizes, int n_in,
                              void* d_out, int out_size)
{
    const float* x   = (const float*)d_in[0];
    const float* h0  = (const float*)d_in[1];
    const float* c0  = (const float*)d_in[2];
    const float* Wih = (const float*)d_in[3];
    const float* Whh = (const float*)d_in[4];
    const float* bih = (const float*)d_in[5];
    const float* bhh = (const float*)d_in[6];
    const float* Wl  = (const float*)d_in[7];
    const float* bl  = (const float*)d_in[8];
    float* out = (float*)d_out;

    const size_t st = (size_t)BB * HH;
    const size_t wS = (size_t)GG * HH;
    const size_t bS = (size_t)GG;

    cudaFuncSetAttribute(fused_rec<0>, cudaFuncAttributeMaxDynamicSharedMemorySize, SM_TOT);
    cudaFuncSetAttribute(fused_rec<1>, cudaFuncAttributeMaxDynamicSharedMemorySize, SM_TOT);

    const int grid = BB / 64;          // 512
    const int gridL = (BB * TT) / 128; // 19968

    // Layer 0: x (fp32) -> hbuf
    fused_rec<0><<<grid, 128, SM_TOT>>>(x, Wih, Whh, bih, bhh, h0, c0);
    // Layer 1: hbuf -> hbuf
    fused_rec<1><<<grid, 128, SM_TOT>>>(x, Wih + wS, Whh + wS, bih + bS, bhh + bS,
                                        h0 + st, c0 + st);
    // Layer 2: hbuf -> hbuf
    fused_rec<1><<<grid, 128, SM_TOT>>>(x, Wih + 2 * wS, Whh + 2 * wS,
                                        bih + 2 * bS, bhh + 2 * bS,
                                        h0 + 2 * st, c0 + 2 * st);
    // Linear head: hbuf -> dout
    lin_kernel<<<gridL, 128>>>(Wl, bl, out);
}

// round 15
// speedup vs baseline: 2.1081x; 1.2678x over previous
#include <cuda_runtime.h>
#include <cuda_bf16.h>
#include <cstdint>

#define BB 32768
#define TT 78
#define HH 27
#define T27 (TT * HH)    // 2106
#define GG 108
#define RB 32            // rows per block

static __device__ unsigned int g_hbuf[(size_t)BB * TT * HH];   // (bf16hi<<16 | bf16lo)

__device__ __forceinline__ float sigf(float x) {
    return __fdividef(1.f, 1.f + __expf(-x));
}
__device__ __forceinline__ float tapx(float x) {
    float r;
    asm("tanh.approx.f32 %0,%1;" : "=f"(r) : "f"(x));
    return r;
}
__device__ __forceinline__ float sig_apx(float x) {
    return fmaf(0.5f, tapx(0.5f * x), 0.5f);
}

__device__ __forceinline__ void cpa4(unsigned s, const void* g) {
    asm volatile("cp.async.ca.shared.global [%0],[%1],4;" :: "r"(s), "l"(g));
}
#define CPC() asm volatile("cp.async.commit_group;" ::: "memory")
#define CPW1() asm volatile("cp.async.wait_group 1;" ::: "memory")
#define CPW0() asm volatile("cp.async.wait_group 0;" ::: "memory")

__device__ __forceinline__ uint32_t su32(const void* p) {
    uint32_t a;
    asm("{.reg .u64 t; cvta.to.shared.u64 t,%1; cvt.u32.u64 %0,t;}" : "=r"(a) : "l"(p));
    return a;
}

#define MMA(C, A, B)                                                          \
    asm volatile(                                                             \
        "mma.sync.aligned.m16n8k16.row.col.f32.bf16.bf16.f32 "                \
        "{%0,%1,%2,%3},{%4,%5,%6,%7},{%8,%9},{%0,%1,%2,%3};"                  \
        : "+f"((C)[0]), "+f"((C)[1]), "+f"((C)[2]), "+f"((C)[3])              \
        : "r"((A)[0]), "r"((A)[1]), "r"((A)[2]), "r"((A)[3]),                 \
          "r"((B)[0]), "r"((B)[1]))

__device__ __forceinline__ void bsplit(float v, unsigned short& h, unsigned short& l) {
    __nv_bfloat16 hb = __float2bfloat16(v);
    __nv_bfloat16 lb = __float2bfloat16(v - __bfloat162float(hb));
    h = __bfloat16_as_ushort(hb);
    l = __bfloat16_as_ushort(lb);
}

// ---- SMEM map: A [p][hl] @ p*8192+hl*4096 (32 rows x 128B each);
//      xring @16384 (+3456/slot); h_sm double @23296 (+3456/slot)
#define SM_XR 16384
#define SM_HS 23296
#define SM_TOT 30208

// ================= Fused layer: per-t MMA of [h|x] @ [Whh|Wih]^T + LSTM cell ========
// Block = 32 batch rows, 128 threads. One __syncthreads per timestep.

template<int SRC>
__global__ void __launch_bounds__(128, 3)
fused_rec(const float* __restrict__ xin,
          const float* __restrict__ Wih, const float* __restrict__ Whh,
          const float* __restrict__ bih, const float* __restrict__ bhh,
          const float* __restrict__ h0, const float* __restrict__ c0)
{
    extern __shared__ char sm[];
    const uint32_t smb = su32(sm);
    unsigned int* h_sm = (unsigned int*)(sm + SM_HS);

    const int tid = threadIdx.x, w = tid >> 5, l = tid & 31;
    const int lq = l >> 2, lr = l & 3, gh = lr & 1;
    const int ntmax = (w == 3) ? 2 : 4;
    const size_t bbase = (size_t)blockIdx.x * RB;

    for (int i = tid; i < 4096; i += 128) ((uint32_t*)sm)[i] = 0;   // zero A tables

    // B fragments
    uint32_t bfh[4][4][2], bfl[4][4][2];
#pragma unroll
    for (int kb = 0; kb < 4; ++kb)
#pragma unroll
    for (int nt = 0; nt < 4; ++nt)
#pragma unroll
    for (int r = 0; r < 2; ++r) {
        int n = w * 32 + nt * 8 + lq, j = n >> 2, g = n & 3;
        int k0 = kb * 16 + r * 8 + 2 * lr;
        float v0 = 0.f, v1 = 0.f;
        if (j < HH) {
            if (k0 < HH) v0 = Whh[(g * HH + j) * HH + k0];
            else if (k0 < 54) v0 = Wih[(g * HH + j) * HH + k0 - HH];
            int k1 = k0 + 1;
            if (k1 < HH) v1 = Whh[(g * HH + j) * HH + k1];
            else if (k1 < 54) v1 = Wih[(g * HH + j) * HH + k1 - HH];
        }
        unsigned short h0u, l0u, h1u, l1u;
        bsplit(v0, h0u, l0u);
        bsplit(v1, h1u, l1u);
        bfh[kb][nt][r] = ((uint32_t)h1u << 16) | h0u;
        bfl[kb][nt][r] = ((uint32_t)l1u << 16) | l0u;
    }

    float bias0[4], bias1[4];
#pragma unroll
    for (int nt = 0; nt < 4; ++nt) {
        int jj = w * 8 + 2 * nt + (lr >> 1);
        int g0 = 2 * gh;
        bias0[nt] = (jj < HH) ? bih[g0 * HH + jj] + bhh[g0 * HH + jj] : 0.f;
        bias1[nt] = (jj < HH) ? bih[(g0 + 1) * HH + jj] + bhh[(g0 + 1) * HH + jj] : 0.f;
    }

    float cReg[8];
#pragma unroll
    for (int mt = 0; mt < 2; ++mt)
#pragma unroll
    for (int nt = 0; nt < 4; ++nt) {
        int jj = w * 8 + 2 * nt + (lr >> 1);
        int row = mt * 16 + lq + (gh ? 8 : 0);
        cReg[mt * 4 + nt] = (jj < HH) ? c0[(bbase + row) * HH + jj] : 0.f;
    }

    __syncthreads();

    // h0 -> As[0] cols 0..26 (warp owns rows w*8 .. w*8+7)
    if (l < HH) {
        for (int rr = 0; rr < 8; ++rr) {
            int row = w * 8 + rr;
            unsigned short hu, lu;
            bsplit(h0[(bbase + row) * HH + l], hu, lu);
            uint32_t a = ((uint32_t)(row * 128 + l * 2)) ^ (uint32_t)((row & 7) << 4);
            ((unsigned short*)sm)[a >> 1] = hu;
            ((unsigned short*)(sm + 4096))[a >> 1] = lu;
        }
    }

    const char* src = SRC ? (const char*)g_hbuf : (const char*)xin;

#pragma unroll
    for (int t0 = 0; t0 < 2; ++t0) {
        if (l < HH) {
            for (int rr = 0; rr < 8; ++rr) {
                int row = w * 8 + rr;
                cpa4(smb + SM_XR + t0 * 3456 + (uint32_t)(row * HH + l) * 4,
                     src + ((bbase + row) * T27 + (size_t)t0 * HH + l) * 4);
            }
        }
        CPC();
    }
    CPW0();
    if (l < HH) {
        for (int rr = 0; rr < 8; ++rr) {
            int row = w * 8 + rr;
            unsigned short hu, lu;
            if (SRC == 0) {
                bsplit(((const float*)(sm + SM_XR))[row * HH + l], hu, lu);
            } else {
                unsigned int u = ((const unsigned int*)(sm + SM_XR))[row * HH + l];
                hu = (unsigned short)(u >> 16);
                lu = (unsigned short)(u & 0xffffu);
            }
            uint32_t a = ((uint32_t)(row * 128 + (HH + l) * 2)) ^ (uint32_t)((row & 7) << 4);
            ((unsigned short*)sm)[a >> 1] = hu;
            ((unsigned short*)(sm + 4096))[a >> 1] = lu;
        }
    }
    __syncthreads();

    int p = 0;
#pragma unroll 1
    for (int t = 0; t < TT; ++t) {
        // issue x_{t+2}
        if (t + 2 < TT && l < HH) {
            for (int rr = 0; rr < 8; ++rr) {
                int row = w * 8 + rr;
                cpa4(smb + SM_XR + (t & 1) * 3456 + (uint32_t)(row * HH + l) * 4,
                     src + ((bbase + row) * T27 + (size_t)(t + 2) * HH + l) * 4);
            }
        }
        CPC();
        CPW1();

        // convert x_{t+1} -> A[p^1] cols 27..53
        if (t + 1 < TT && l < HH) {
            char* hiB = sm + (p ^ 1) * 8192;
            char* loB = hiB + 4096;
            const char* slot = sm + SM_XR + ((t + 1) & 1) * 3456;
            for (int rr = 0; rr < 8; ++rr) {
                int row = w * 8 + rr;
                unsigned short hu, lu;
                if (SRC == 0) {
                    bsplit(((const float*)slot)[row * HH + l], hu, lu);
                } else {
                    unsigned int u = ((const unsigned int*)slot)[row * HH + l];
                    hu = (unsigned short)(u >> 16);
                    lu = (unsigned short)(u & 0xffffu);
                }
                uint32_t a = ((uint32_t)(row * 128 + (HH + l) * 2)) ^
                             (uint32_t)((row & 7) << 4);
                ((unsigned short*)hiB)[a >> 1] = hu;
                ((unsigned short*)loB)[a >> 1] = lu;
            }
        }

        // flush h_{t-1} (slot (t-1)&1; epilogue below writes slot t&1 — no race)
        if (t >= 1) {
            const unsigned int* hsrc = h_sm + ((t - 1) & 1) * (RB * HH);
#pragma unroll
            for (int it = 0; it < 7; ++it) {
                int idx = it * 128 + tid;
                if (idx < RB * HH) {
                    int row = idx / HH, k = idx - row * HH;
                    g_hbuf[(bbase + row) * T27 + (size_t)(t - 1) * HH + k] = hsrc[idx];
                }
            }
        }

        const uint32_t hiBase = smb + p * 8192;
        const uint32_t loBase = hiBase + 4096;
        char* hiW = sm + (p ^ 1) * 8192;
        char* loW = hiW + 4096;
        unsigned int* hdst = h_sm + (t & 1) * (RB * HH);

#pragma unroll
        for (int mt = 0; mt < 2; ++mt) {
            const int row0 = mt * 16 + lq;
            const uint32_t xr = (uint32_t)((row0 & 7) << 4);
            const uint32_t rb0 = (uint32_t)(row0 * 128);
            const uint32_t rb1 = (uint32_t)((row0 + 8) * 128);
            uint32_t Ah[4][4], Al[4][4];
#pragma unroll
            for (int s = 0; s < 4; ++s) {
                uint32_t cb = (uint32_t)(s * 32 + 4 * lr);
                asm("ld.shared.b32 %0,[%1];" : "=r"(Ah[s][0]) : "r"(hiBase + ((rb0 + cb) ^ xr)));
                asm("ld.shared.b32 %0,[%1];" : "=r"(Ah[s][1]) : "r"(hiBase + ((rb1 + cb) ^ xr)));
                asm("ld.shared.b32 %0,[%1];" : "=r"(Ah[s][2]) : "r"(hiBase + ((rb0 + cb + 16) ^ xr)));
                asm("ld.shared.b32 %0,[%1];" : "=r"(Ah[s][3]) : "r"(hiBase + ((rb1 + cb + 16) ^ xr)));
                asm("ld.shared.b32 %0,[%1];" : "=r"(Al[s][0]) : "r"(loBase + ((rb0 + cb) ^ xr)));
                asm("ld.shared.b32 %0,[%1];" : "=r"(Al[s][1]) : "r"(loBase + ((rb1 + cb) ^ xr)));
                asm("ld.shared.b32 %0,[%1];" : "=r"(Al[s][2]) : "r"(loBase + ((rb0 + cb + 16) ^ xr)));
                asm("ld.shared.b32 %0,[%1];" : "=r"(Al[s][3]) : "r"(loBase + ((rb1 + cb + 16) ^ xr)));
            }
#pragma unroll
            for (int nt = 0; nt < 4; ++nt) {
                if (nt < ntmax) {
                    // two independent 6-deep MMA chains (halved dependency chain)
                    float acc[4] = {bias0[nt], bias1[nt], bias0[nt], bias1[nt]};
                    float ac2[4] = {0.f, 0.f, 0.f, 0.f};
#pragma unroll
                    for (int s = 0; s < 4; ++s) {
                        MMA(acc, Ah[s], bfh[s][nt]);
                        MMA(ac2, Ah[s], bfl[s][nt]);
                    }
#pragma unroll
                    for (int s = 0; s < 4; ++s) MMA(ac2, Al[s], bfh[s][nt]);
                    acc[0] += ac2[0];
                    acc[1] += ac2[1];
                    acc[2] += ac2[2];
                    acc[3] += ac2[3];

                    float v0 = __shfl_xor_sync(0xffffffffu, acc[0], 1);
                    float v1 = __shfl_xor_sync(0xffffffffu, acc[1], 1);
                    float v2 = __shfl_xor_sync(0xffffffffu, acc[2], 1);
                    float v3 = __shfl_xor_sync(0xffffffffu, acc[3], 1);
                    int row;
                    float xi, xf, xg, xo;
                    if (gh == 0) { row = row0;     xi = acc[0]; xf = acc[1]; xg = v0; xo = v1; }
                    else         { row = row0 + 8; xi = v2; xf = v3; xg = acc[2]; xo = acc[3]; }
                    float gi = sig_apx(xi), gf = sigf(xf), gg = tapx(xg), go = sig_apx(xo);
                    float cc = fmaf(gf, cReg[mt * 4 + nt], gi * gg);
                    cReg[mt * 4 + nt] = cc;
                    float hv = go * tapx(cc);
                    int jj = w * 8 + 2 * nt + (lr >> 1);
                    if (jj < HH) {
                        unsigned short hu, lu;
                        bsplit(hv, hu, lu);
                        uint32_t a = ((uint32_t)(row * 128 + jj * 2)) ^
                                     (uint32_t)((row & 7) << 4);
                        ((unsigned short*)hiW)[a >> 1] = hu;
                        ((unsigned short*)loW)[a >> 1] = lu;
                        hdst[row * HH + jj] = ((unsigned int)hu << 16) | lu;
                    }
                }
            }
        }
        __syncthreads();
        p ^= 1;
    }

    // flush final h_{TT-1}
    {
        const unsigned int* hsrc = h_sm + ((TT - 1) & 1) * (RB * HH);
#pragma unroll
        for (int it = 0; it < 7; ++it) {
            int idx = it * 128 + tid;
            if (idx < RB * HH) {
                int row = idx / HH, k = idx - row * HH;
                g_hbuf[(bbase + row) * T27 + (size_t)(TT - 1) * HH + k] = hsrc[idx];
            }
        }
    }
}

// ================= Final linear: dout = h @ Wl^T + bl (HMMA) =================

__global__ void __launch_bounds__(128, 4)
lin_kernel(const float* __restrict__ Wl, const float* __restrict__ bl,
           float* __restrict__ dout)
{
    __shared__ __align__(16) unsigned short AsH[128 * 64];
    __shared__ __align__(16) unsigned short AsL[128 * 64];

    const int tid = threadIdx.x, w = tid >> 5, l = tid & 31;
    const int lq = l >> 2, lr = l & 3;

    for (int i = tid; i < 128 * 64; i += 128) { AsH[i] = 0; AsL[i] = 0; }

    uint32_t bfh[2][4][2], bfl[2][4][2];
#pragma unroll
    for (int kb = 0; kb < 2; ++kb)
#pragma unroll
    for (int nt = 0; nt < 4; ++nt)
#pragma unroll
    for (int r = 0; r < 2; ++r) {
        int n = nt * 8 + lq;
        int k0 = kb * 16 + r * 8 + 2 * lr;
        float v0 = (n < HH && k0 < HH) ? Wl[n * HH + k0] : 0.f;
        float v1 = (n < HH && k0 + 1 < HH) ? Wl[n * HH + k0 + 1] : 0.f;
        unsigned short h0u, l0u, h1u, l1u;
        bsplit(v0, h0u, l0u);
        bsplit(v1, h1u, l1u);
        bfh[kb][nt][r] = ((uint32_t)h1u << 16) | h0u;
        bfl[kb][nt][r] = ((uint32_t)l1u << 16) | l0u;
    }
    float2 bias[4];
#pragma unroll
    for (int nt = 0; nt < 4; ++nt) {
        int n0 = nt * 8 + 2 * lr;
        bias[nt].x = (n0 < HH) ? bl[n0] : 0.f;
        bias[nt].y = (n0 + 1 < HH) ? bl[n0 + 1] : 0.f;
    }
    __syncthreads();

    const size_t tile = blockIdx.x;
    const unsigned int* hb = g_hbuf + tile * (size_t)(128 * HH);
    for (int i = tid; i < 128 * HH; i += 128) {
        unsigned int u = hb[i];
        int row = i / HH, k = i - row * HH;
        uint32_t a = ((uint32_t)(row * 128 + k * 2)) ^ (uint32_t)((row & 7) << 4);
        AsH[a >> 1] = (unsigned short)(u >> 16);
        AsL[a >> 1] = (unsigned short)(u & 0xffffu);
    }
    __syncthreads();

    const uint32_t hiB = su32(AsH), loB = su32(AsL);
#pragma unroll
    for (int mi = 0; mi < 2; ++mi) {
        const int mt = w * 2 + mi;
        const int row0 = mt * 16 + lq;
        const uint32_t xr = (uint32_t)((row0 & 7) << 4);
        const uint32_t rb0 = (uint32_t)(row0 * 128);
        const uint32_t rb1 = (uint32_t)((row0 + 8) * 128);
        uint32_t Ah[2][4], Al[2][4];
#pragma unroll
        for (int s = 0; s < 2; ++s) {
            uint32_t cb = (uint32_t)(s * 32 + 4 * lr);
            asm("ld.shared.b32 %0,[%1];" : "=r"(Ah[s][0]) : "r"(hiB + ((rb0 + cb) ^ xr)));
            asm("ld.shared.b32 %0,[%1];" : "=r"(Ah[s][1]) : "r"(hiB + ((rb1 + cb) ^ xr)));
            asm("ld.shared.b32 %0,[%1];" : "=r"(Ah[s][2]) : "r"(hiB + ((rb0 + cb + 16) ^ xr)));
            asm("ld.shared.b32 %0,[%1];" : "=r"(Ah[s][3]) : "r"(hiB + ((rb1 + cb + 16) ^ xr)));
            asm("ld.shared.b32 %0,[%1];" : "=r"(Al[s][0]) : "r"(loB + ((rb0 + cb) ^ xr)));
            asm("ld.shared.b32 %0,[%1];" : "=r"(Al[s][1]) : "r"(loB + ((rb1 + cb) ^ xr)));
            asm("ld.shared.b32 %0,[%1];" : "=r"(Al[s][2]) : "r"(loB + ((rb0 + cb + 16) ^ xr)));
            asm("ld.shared.b32 %0,[%1];" : "=r"(Al[s][3]) : "r"(loB + ((rb1 + cb + 16) ^ xr)));
        }
#pragma unroll
        for (int nt = 0; nt < 4; ++nt) {
            float acc[4] = {bias[nt].x, bias[nt].y, bias[nt].x, bias[nt].y};
            float ac2[4] = {0.f, 0.f, 0.f, 0.f};
#pragma unroll
            for (int s = 0; s < 2; ++s) {
                MMA(acc, Ah[s], bfh[s][nt]);
                MMA(ac2, Ah[s], bfl[s][nt]);
            }
#pragma unroll
            for (int s = 0; s < 2; ++s) MMA(ac2, Al[s], bfh[s][nt]);
            acc[0] += ac2[0];
            acc[1] += ac2[1];
            acc[2] += ac2[2];
            acc[3] += ac2[3];
            int n0 = nt * 8 + 2 * lr;
            float* d0 = dout + (tile * 128 + row0) * (size_t)HH;
            float* d1 = dout + (tile * 128 + row0 + 8) * (size_t)HH;
            if (n0 < HH)     { d0[n0] = acc[0];     d1[n0] = acc[2]; }
            if (n0 + 1 < HH) { d0[n0 + 1] = acc[1]; d1[n0 + 1] = acc[3]; }
        }
    }
}

// ================= host =================
extern "C" void kernel_launch(void* const* d_in, const int* in_sizes, int n_in,
                              void* d_out, int out_size)
{
    const float* x   = (const float*)d_in[0];
    const float* h0  = (const float*)d_in[1];
    const float* c0  = (const float*)d_in[2];
    const float* Wih = (const float*)d_in[3];
    const float* Whh = (const float*)d_in[4];
    const float* bih = (const float*)d_in[5];
    const float* bhh = (const float*)d_in[6];
    const float* Wl  = (const float*)d_in[7];
    const float* bl  = (const float*)d_in[8];
    float* out = (float*)d_out;

    const size_t st = (size_t)BB * HH;
    const size_t wS = (size_t)GG * HH;
    const size_t bS = (size_t)GG;

    cudaFuncSetAttribute(fused_rec<0>, cudaFuncAttributeMaxDynamicSharedMemorySize, SM_TOT);
    cudaFuncSetAttribute(fused_rec<1>, cudaFuncAttributeMaxDynamicSharedMemorySize, SM_TOT);

    const int grid = BB / RB;          // 1024
    const int gridL = (BB * TT) / 128; // 19968

    fused_rec<0><<<grid, 128, SM_TOT>>>(x, Wih, Whh, bih, bhh, h0, c0);
    fused_rec<1><<<grid, 128, SM_TOT>>>(x, Wih + wS, Whh + wS, bih + bS, bhh + bS,
                                        h0 + st, c0 + st);
    fused_rec<1><<<grid, 128, SM_TOT>>>(x, Wih + 2 * wS, Whh + 2 * wS,
                                        bih + 2 * bS, bhh + 2 * bS,
                                        h0 + 2 * st, c0 + 2 * st);
    lin_kernel<<<gridL, 128>>>(Wl, bl, out);
}

// round 16
// speedup vs baseline: 2.3078x; 1.0947x over previous
#include <cuda_runtime.h>
#include <cuda_bf16.h>
#include <cstdint>

#define BB 32768
#define TT 78
#define HH 27
#define T27 (TT * HH)    // 2106
#define GG 108
#define RB 32            // rows per block

static __device__ unsigned int g_hbuf[(size_t)BB * TT * HH];   // (bf16hi<<16 | bf16lo)

__device__ __forceinline__ float sigf(float x) {
    return __fdividef(1.f, 1.f + __expf(-x));
}
__device__ __forceinline__ float tapx(float x) {
    float r;
    asm("tanh.approx.f32 %0,%1;" : "=f"(r) : "f"(x));
    return r;
}
__device__ __forceinline__ float sig_apx(float x) {
    return fmaf(0.5f, tapx(0.5f * x), 0.5f);
}

__device__ __forceinline__ void cpa4(unsigned s, const void* g) {
    asm volatile("cp.async.ca.shared.global [%0],[%1],4;" :: "r"(s), "l"(g));
}
#define CPC() asm volatile("cp.async.commit_group;" ::: "memory")
#define CPW1() asm volatile("cp.async.wait_group 1;" ::: "memory")
#define CPW0() asm volatile("cp.async.wait_group 0;" ::: "memory")

__device__ __forceinline__ uint32_t su32(const void* p) {
    uint32_t a;
    asm("{.reg .u64 t; cvta.to.shared.u64 t,%1; cvt.u32.u64 %0,t;}" : "=r"(a) : "l"(p));
    return a;
}

#define MMA(C, A, B)                                                          \
    asm volatile(                                                             \
        "mma.sync.aligned.m16n8k16.row.col.f32.bf16.bf16.f32 "                \
        "{%0,%1,%2,%3},{%4,%5,%6,%7},{%8,%9},{%0,%1,%2,%3};"                  \
        : "+f"((C)[0]), "+f"((C)[1]), "+f"((C)[2]), "+f"((C)[3])              \
        : "r"((A)[0]), "r"((A)[1]), "r"((A)[2]), "r"((A)[3]),                 \
          "r"((B)[0]), "r"((B)[1]))

__device__ __forceinline__ void bsplit(float v, unsigned short& h, unsigned short& l) {
    __nv_bfloat16 hb = __float2bfloat16(v);
    __nv_bfloat16 lb = __float2bfloat16(v - __bfloat162float(hb));
    h = __bfloat16_as_ushort(hb);
    l = __bfloat16_as_ushort(lb);
}

// SMEM: A [p][hl] @ p*8192+hl*4096 ; xring @16384 (+3456/slot); h_sm @23296 (+3456/slot)
#define SM_XR 16384
#define SM_HS 23296
#define SM_TOT 30208

// ================= Fused layer body: per-t MMA [h|x]@[Whh|Wih]^T + LSTM cell.
// DOLIN: linear head folded in (reuses rec's A fragments; emits out[t-1] at iter t).

template<int SRC, int DOLIN>
__device__ __forceinline__ void fused_body(
    const float* __restrict__ xin,
    const float* __restrict__ Wih, const float* __restrict__ Whh,
    const float* __restrict__ bih, const float* __restrict__ bhh,
    const float* __restrict__ h0, const float* __restrict__ c0,
    const float* __restrict__ Wl, const float* __restrict__ bl,
    float* __restrict__ dout, char* sm)
{
    const uint32_t smb = su32(sm);
    unsigned int* h_sm = (unsigned int*)(sm + SM_HS);

    const int tid = threadIdx.x, w = tid >> 5, l = tid & 31;
    const int lq = l >> 2, lr = l & 3, gh = lr & 1;
    const int ntmax = (w == 3) ? 2 : 4;
    const size_t bbase = (size_t)blockIdx.x * RB;

    for (int i = tid; i < 4096; i += 128) ((uint32_t*)sm)[i] = 0;

    // rec B fragments
    uint32_t bfh[4][4][2], bfl[4][4][2];
#pragma unroll
    for (int kb = 0; kb < 4; ++kb)
#pragma unroll
    for (int nt = 0; nt < 4; ++nt)
#pragma unroll
    for (int r = 0; r < 2; ++r) {
        int n = w * 32 + nt * 8 + lq, j = n >> 2, g = n & 3;
        int k0 = kb * 16 + r * 8 + 2 * lr;
        float v0 = 0.f, v1 = 0.f;
        if (j < HH) {
            if (k0 < HH) v0 = Whh[(g * HH + j) * HH + k0];
            else if (k0 < 54) v0 = Wih[(g * HH + j) * HH + k0 - HH];
            int k1 = k0 + 1;
            if (k1 < HH) v1 = Whh[(g * HH + j) * HH + k1];
            else if (k1 < 54) v1 = Wih[(g * HH + j) * HH + k1 - HH];
        }
        unsigned short h0u, l0u, h1u, l1u;
        bsplit(v0, h0u, l0u);
        bsplit(v1, h1u, l1u);
        bfh[kb][nt][r] = ((uint32_t)h1u << 16) | h0u;
        bfl[kb][nt][r] = ((uint32_t)l1u << 16) | l0u;
    }

    // lin B fragments (DOLIN): warp w owns out cols n = 8w+lq; K=32, zeros at k>=27
    uint32_t wlh[2][2], wll[2][2];
    float2 lbias = make_float2(0.f, 0.f);
    if (DOLIN) {
#pragma unroll
        for (int kb = 0; kb < 2; ++kb)
#pragma unroll
        for (int r = 0; r < 2; ++r) {
            int n = w * 8 + lq;
            int k0 = kb * 16 + r * 8 + 2 * lr;
            float v0 = (n < HH && k0 < HH) ? Wl[n * HH + k0] : 0.f;
            float v1 = (n < HH && k0 + 1 < HH) ? Wl[n * HH + k0 + 1] : 0.f;
            unsigned short h0u, l0u, h1u, l1u;
            bsplit(v0, h0u, l0u);
            bsplit(v1, h1u, l1u);
            wlh[kb][r] = ((uint32_t)h1u << 16) | h0u;
            wll[kb][r] = ((uint32_t)l1u << 16) | l0u;
        }
        int n0 = w * 8 + 2 * lr;
        lbias.x = (n0 < HH) ? bl[n0] : 0.f;
        lbias.y = (n0 + 1 < HH) ? bl[n0 + 1] : 0.f;
    }

    float bias0[4], bias1[4];
#pragma unroll
    for (int nt = 0; nt < 4; ++nt) {
        int jj = w * 8 + 2 * nt + (lr >> 1);
        int g0 = 2 * gh;
        bias0[nt] = (jj < HH) ? bih[g0 * HH + jj] + bhh[g0 * HH + jj] : 0.f;
        bias1[nt] = (jj < HH) ? bih[(g0 + 1) * HH + jj] + bhh[(g0 + 1) * HH + jj] : 0.f;
    }

    float cReg[8];
#pragma unroll
    for (int mt = 0; mt < 2; ++mt)
#pragma unroll
    for (int nt = 0; nt < 4; ++nt) {
        int jj = w * 8 + 2 * nt + (lr >> 1);
        int row = mt * 16 + lq + (gh ? 8 : 0);
        cReg[mt * 4 + nt] = (jj < HH) ? c0[(bbase + row) * HH + jj] : 0.f;
    }

    __syncthreads();

    if (l < HH) {
        for (int rr = 0; rr < 8; ++rr) {
            int row = w * 8 + rr;
            unsigned short hu, lu;
            bsplit(h0[(bbase + row) * HH + l], hu, lu);
            uint32_t a = ((uint32_t)(row * 128 + l * 2)) ^ (uint32_t)((row & 7) << 4);
            ((unsigned short*)sm)[a >> 1] = hu;
            ((unsigned short*)(sm + 4096))[a >> 1] = lu;
        }
    }

    const char* src = SRC ? (const char*)g_hbuf : (const char*)xin;

#pragma unroll
    for (int t0 = 0; t0 < 2; ++t0) {
        if (l < HH) {
            for (int rr = 0; rr < 8; ++rr) {
                int row = w * 8 + rr;
                cpa4(smb + SM_XR + t0 * 3456 + (uint32_t)(row * HH + l) * 4,
                     src + ((bbase + row) * T27 + (size_t)t0 * HH + l) * 4);
            }
        }
        CPC();
    }
    CPW0();
    if (l < HH) {
        for (int rr = 0; rr < 8; ++rr) {
            int row = w * 8 + rr;
            unsigned short hu, lu;
            if (SRC == 0) {
                bsplit(((const float*)(sm + SM_XR))[row * HH + l], hu, lu);
            } else {
                unsigned int u = ((const unsigned int*)(sm + SM_XR))[row * HH + l];
                hu = (unsigned short)(u >> 16);
                lu = (unsigned short)(u & 0xffffu);
            }
            uint32_t a = ((uint32_t)(row * 128 + (HH + l) * 2)) ^ (uint32_t)((row & 7) << 4);
            ((unsigned short*)sm)[a >> 1] = hu;
            ((unsigned short*)(sm + 4096))[a >> 1] = lu;
        }
    }
    __syncthreads();

    int p = 0;
#pragma unroll 1
    for (int t = 0; t < TT; ++t) {
        if (t + 2 < TT && l < HH) {
            for (int rr = 0; rr < 8; ++rr) {
                int row = w * 8 + rr;
                cpa4(smb + SM_XR + (t & 1) * 3456 + (uint32_t)(row * HH + l) * 4,
                     src + ((bbase + row) * T27 + (size_t)(t + 2) * HH + l) * 4);
            }
        }
        CPC();
        CPW1();

        if (t + 1 < TT && l < HH) {
            char* hiB = sm + (p ^ 1) * 8192;
            char* loB = hiB + 4096;
            const char* slot = sm + SM_XR + ((t + 1) & 1) * 3456;
            for (int rr = 0; rr < 8; ++rr) {
                int row = w * 8 + rr;
                unsigned short hu, lu;
                if (SRC == 0) {
                    bsplit(((const float*)slot)[row * HH + l], hu, lu);
                } else {
                    unsigned int u = ((const unsigned int*)slot)[row * HH + l];
                    hu = (unsigned short)(u >> 16);
                    lu = (unsigned short)(u & 0xffffu);
                }
                uint32_t a = ((uint32_t)(row * 128 + (HH + l) * 2)) ^
                             (uint32_t)((row & 7) << 4);
                ((unsigned short*)hiB)[a >> 1] = hu;
                ((unsigned short*)loB)[a >> 1] = lu;
            }
        }

        if (!DOLIN && t >= 1) {
            const unsigned int* hsrc = h_sm + ((t - 1) & 1) * (RB * HH);
#pragma unroll
            for (int it = 0; it < 7; ++it) {
                int idx = it * 128 + tid;
                if (idx < RB * HH) {
                    int row = idx / HH, k = idx - row * HH;
                    g_hbuf[(bbase + row) * T27 + (size_t)(t - 1) * HH + k] = hsrc[idx];
                }
            }
        }

        const uint32_t hiBase = smb + p * 8192;
        const uint32_t loBase = hiBase + 4096;
        char* hiW = sm + (p ^ 1) * 8192;
        char* loW = hiW + 4096;
        unsigned int* hdst = h_sm + (t & 1) * (RB * HH);

#pragma unroll
        for (int mt = 0; mt < 2; ++mt) {
            const int row0 = mt * 16 + lq;
            const uint32_t xr = (uint32_t)((row0 & 7) << 4);
            const uint32_t rb0 = (uint32_t)(row0 * 128);
            const uint32_t rb1 = (uint32_t)((row0 + 8) * 128);
            uint32_t Ah[4][4], Al[4][4];
#pragma unroll
            for (int s = 0; s < 4; ++s) {
                uint32_t cb = (uint32_t)(s * 32 + 4 * lr);
                asm("ld.shared.b32 %0,[%1];" : "=r"(Ah[s][0]) : "r"(hiBase + ((rb0 + cb) ^ xr)));
                asm("ld.shared.b32 %0,[%1];" : "=r"(Ah[s][1]) : "r"(hiBase + ((rb1 + cb) ^ xr)));
                asm("ld.shared.b32 %0,[%1];" : "=r"(Ah[s][2]) : "r"(hiBase + ((rb0 + cb + 16) ^ xr)));
                asm("ld.shared.b32 %0,[%1];" : "=r"(Ah[s][3]) : "r"(hiBase + ((rb1 + cb + 16) ^ xr)));
                asm("ld.shared.b32 %0,[%1];" : "=r"(Al[s][0]) : "r"(loBase + ((rb0 + cb) ^ xr)));
                asm("ld.shared.b32 %0,[%1];" : "=r"(Al[s][1]) : "r"(loBase + ((rb1 + cb) ^ xr)));
                asm("ld.shared.b32 %0,[%1];" : "=r"(Al[s][2]) : "r"(loBase + ((rb0 + cb + 16) ^ xr)));
                asm("ld.shared.b32 %0,[%1];" : "=r"(Al[s][3]) : "r"(loBase + ((rb1 + cb + 16) ^ xr)));
            }

            // DOLIN: emit out[t-1] = h_{t-1} @ Wl^T + bl using same fragments (K=32)
            if (DOLIN && t >= 1) {
                float la[4] = {lbias.x, lbias.y, lbias.x, lbias.y};
                float lb2[4] = {0.f, 0.f, 0.f, 0.f};
                MMA(la, Ah[0], wlh[0]);
                MMA(lb2, Ah[0], wll[0]);
                MMA(la, Ah[1], wlh[1]);
                MMA(lb2, Ah[1], wll[1]);
                MMA(lb2, Al[0], wlh[0]);
                MMA(lb2, Al[1], wlh[1]);
                int n0 = w * 8 + 2 * lr;
                float* d0 = dout + (bbase + row0) * (size_t)T27 + (size_t)(t - 1) * HH;
                float* d1 = dout + (bbase + row0 + 8) * (size_t)T27 + (size_t)(t - 1) * HH;
                if (n0 < HH)     { d0[n0] = la[0] + lb2[0];     d1[n0] = la[2] + lb2[2]; }
                if (n0 + 1 < HH) { d0[n0 + 1] = la[1] + lb2[1]; d1[n0 + 1] = la[3] + lb2[3]; }
            }

#pragma unroll
            for (int nt = 0; nt < 4; ++nt) {
                if (nt < ntmax) {
                    float acc[4] = {bias0[nt], bias1[nt], bias0[nt], bias1[nt]};
                    float ac2[4] = {0.f, 0.f, 0.f, 0.f};
#pragma unroll
                    for (int s = 0; s < 4; ++s) {
                        MMA(acc, Ah[s], bfh[s][nt]);
                        MMA(ac2, Ah[s], bfl[s][nt]);
                    }
#pragma unroll
                    for (int s = 0; s < 4; ++s) MMA(ac2, Al[s], bfh[s][nt]);
                    acc[0] += ac2[0];
                    acc[1] += ac2[1];
                    acc[2] += ac2[2];
                    acc[3] += ac2[3];

                    float v0 = __shfl_xor_sync(0xffffffffu, acc[0], 1);
                    float v1 = __shfl_xor_sync(0xffffffffu, acc[1], 1);
                    float v2 = __shfl_xor_sync(0xffffffffu, acc[2], 1);
                    float v3 = __shfl_xor_sync(0xffffffffu, acc[3], 1);
                    int row;
                    float xi, xf, xg, xo;
                    if (gh == 0) { row = row0;     xi = acc[0]; xf = acc[1]; xg = v0; xo = v1; }
                    else         { row = row0 + 8; xi = v2; xf = v3; xg = acc[2]; xo = acc[3]; }
                    float gi = sig_apx(xi), gf = sigf(xf), gg = tapx(xg), go = sig_apx(xo);
                    float cc = fmaf(gf, cReg[mt * 4 + nt], gi * gg);
                    cReg[mt * 4 + nt] = cc;
                    float hv = go * tapx(cc);
                    int jj = w * 8 + 2 * nt + (lr >> 1);
                    if (jj < HH) {
                        unsigned short hu, lu;
                        bsplit(hv, hu, lu);
                        uint32_t a = ((uint32_t)(row * 128 + jj * 2)) ^
                                     (uint32_t)((row & 7) << 4);
                        ((unsigned short*)hiW)[a >> 1] = hu;
                        ((unsigned short*)loW)[a >> 1] = lu;
                        if (!DOLIN) hdst[row * HH + jj] = ((unsigned int)hu << 16) | lu;
                    }
                }
            }
        }
        __syncthreads();
        p ^= 1;
    }

    if (!DOLIN) {
        const unsigned int* hsrc = h_sm + ((TT - 1) & 1) * (RB * HH);
#pragma unroll
        for (int it = 0; it < 7; ++it) {
            int idx = it * 128 + tid;
            if (idx < RB * HH) {
                int row = idx / HH, k = idx - row * HH;
                g_hbuf[(bbase + row) * T27 + (size_t)(TT - 1) * HH + k] = hsrc[idx];
            }
        }
    } else {
        // emit out[TT-1] from h_{TT-1} now in A[p] cols 0..26
        const uint32_t hiBase = smb + p * 8192;
        const uint32_t loBase = hiBase + 4096;
#pragma unroll
        for (int mt = 0; mt < 2; ++mt) {
            const int row0 = mt * 16 + lq;
            const uint32_t xr = (uint32_t)((row0 & 7) << 4);
            const uint32_t rb0 = (uint32_t)(row0 * 128);
            const uint32_t rb1 = (uint32_t)((row0 + 8) * 128);
            uint32_t Ah[2][4], Al[2][4];
#pragma unroll
            for (int s = 0; s < 2; ++s) {
                uint32_t cb = (uint32_t)(s * 32 + 4 * lr);
                asm("ld.shared.b32 %0,[%1];" : "=r"(Ah[s][0]) : "r"(hiBase + ((rb0 + cb) ^ xr)));
                asm("ld.shared.b32 %0,[%1];" : "=r"(Ah[s][1]) : "r"(hiBase + ((rb1 + cb) ^ xr)));
                asm("ld.shared.b32 %0,[%1];" : "=r"(Ah[s][2]) : "r"(hiBase + ((rb0 + cb + 16) ^ xr)));
                asm("ld.shared.b32 %0,[%1];" : "=r"(Ah[s][3]) : "r"(hiBase + ((rb1 + cb + 16) ^ xr)));
                asm("ld.shared.b32 %0,[%1];" : "=r"(Al[s][0]) : "r"(loBase + ((rb0 + cb) ^ xr)));
                asm("ld.shared.b32 %0,[%1];" : "=r"(Al[s][1]) : "r"(loBase + ((rb1 + cb) ^ xr)));
                asm("ld.shared.b32 %0,[%1];" : "=r"(Al[s][2]) : "r"(loBase + ((rb0 + cb + 16) ^ xr)));
                asm("ld.shared.b32 %0,[%1];" : "=r"(Al[s][3]) : "r"(loBase + ((rb1 + cb + 16) ^ xr)));
            }
            float la[4] = {lbias.x, lbias.y, lbias.x, lbias.y};
            float lb2[4] = {0.f, 0.f, 0.f, 0.f};
            MMA(la, Ah[0], wlh[0]);
            MMA(lb2, Ah[0], wll[0]);
            MMA(la, Ah[1], wlh[1]);
            MMA(lb2, Ah[1], wll[1]);
            MMA(lb2, Al[0], wlh[0]);
            MMA(lb2, Al[1], wlh[1]);
            int n0 = w * 8 + 2 * lr;
            float* d0 = dout + (bbase + row0) * (size_t)T27 + (size_t)(TT - 1) * HH;
            float* d1 = dout + (bbase + row0 + 8) * (size_t)T27 + (size_t)(TT - 1) * HH;
            if (n0 < HH)     { d0[n0] = la[0] + lb2[0];     d1[n0] = la[2] + lb2[2]; }
            if (n0 + 1 < HH) { d0[n0 + 1] = la[1] + lb2[1]; d1[n0 + 1] = la[3] + lb2[3]; }
        }
    }
}

// wrappers: layers 0/1 at occupancy 4 (reg-capped 128), layer 2 (+lin) at 3
__global__ void __launch_bounds__(128, 4)
fr_l0(const float* xin, const float* Wih, const float* Whh,
      const float* bih, const float* bhh, const float* h0, const float* c0)
{
    extern __shared__ char sm[];
    fused_body<0, 0>(xin, Wih, Whh, bih, bhh, h0, c0, nullptr, nullptr, nullptr, sm);
}
__global__ void __launch_bounds__(128, 4)
fr_l1(const float* xin, const float* Wih, const float* Whh,
      const float* bih, const float* bhh, const float* h0, const float* c0)
{
    extern __shared__ char sm[];
    fused_body<1, 0>(xin, Wih, Whh, bih, bhh, h0, c0, nullptr, nullptr, nullptr, sm);
}
__global__ void __launch_bounds__(128, 3)
fr_l2(const float* xin, const float* Wih, const float* Whh,
      const float* bih, const float* bhh, const float* h0, const float* c0,
      const float* Wl, const float* bl, float* dout)
{
    extern __shared__ char sm[];
    fused_body<1, 1>(xin, Wih, Whh, bih, bhh, h0, c0, Wl, bl, dout, sm);
}

// ================= host =================
extern "C" void kernel_launch(void* const* d_in, const int* in_sizes, int n_in,
                              void* d_out, int out_size)
{
    const float* x   = (const float*)d_in[0];
    const float* h0  = (const float*)d_in[1];
    const float* c0  = (const float*)d_in[2];
    const float* Wih = (const float*)d_in[3];
    const float* Whh = (const float*)d_in[4];
    const float* bih = (const float*)d_in[5];
    const float* bhh = (const float*)d_in[6];
    const float* Wl  = (const float*)d_in[7];
    const float* bl  = (const float*)d_in[8];
    float* out = (float*)d_out;

    const size_t st = (size_t)BB * HH;
    const size_t wS = (size_t)GG * HH;
    const size_t bS = (size_t)GG;

    cudaFuncSetAttribute(fr_l0, cudaFuncAttributeMaxDynamicSharedMemorySize, SM_TOT);
    cudaFuncSetAttribute(fr_l1, cudaFuncAttributeMaxDynamicSharedMemorySize, SM_TOT);
    cudaFuncSetAttribute(fr_l2, cudaFuncAttributeMaxDynamicSharedMemorySize, SM_TOT);

    const int grid = BB / RB;   // 1024

    fr_l0<<<grid, 128, SM_TOT>>>(x, Wih, Whh, bih, bhh, h0, c0);
    fr_l1<<<grid, 128, SM_TOT>>>(x, Wih + wS, Whh + wS, bih + bS, bhh + bS,
                                 h0 + st, c0 + st);
    fr_l2<<<grid, 128, SM_TOT>>>(x, Wih + 2 * wS, Whh + 2 * wS,
                                 bih + 2 * bS, bhh + 2 * bS,
                                 h0 + 2 * st, c0 + 2 * st, Wl, bl, out);
}

// round 17
// speedup vs baseline: 2.7105x; 1.1745x over previous
#include <cuda_runtime.h>
#include <cuda_bf16.h>
#include <cstdint>

#define BB 32768
#define TT 78
#define HH 27
#define T27 (TT * HH)    // 2106
#define GG 108
#define RB 32            // rows per block

static __device__ unsigned int g_hbuf[(size_t)BB * TT * HH];   // (bf16hi<<16 | bf16lo)

__device__ __forceinline__ float sigf(float x) {
    return __fdividef(1.f, 1.f + __expf(-x));
}
__device__ __forceinline__ float tapx(float x) {
    float r;
    asm("tanh.approx.f32 %0,%1;" : "=f"(r) : "f"(x));
    return r;
}
__device__ __forceinline__ float sig_apx(float x) {
    return fmaf(0.5f, tapx(0.5f * x), 0.5f);
}

__device__ __forceinline__ void cpa4(unsigned s, const void* g) {
    asm volatile("cp.async.ca.shared.global [%0],[%1],4;" :: "r"(s), "l"(g));
}
#define CPC() asm volatile("cp.async.commit_group;" ::: "memory")
#define CPW1() asm volatile("cp.async.wait_group 1;" ::: "memory")
#define CPW0() asm volatile("cp.async.wait_group 0;" ::: "memory")

__device__ __forceinline__ uint32_t su32(const void* p) {
    uint32_t a;
    asm("{.reg .u64 t; cvta.to.shared.u64 t,%1; cvt.u32.u64 %0,t;}" : "=r"(a) : "l"(p));
    return a;
}

#define MMA(C, A, B)                                                          \
    asm volatile(                                                             \
        "mma.sync.aligned.m16n8k16.row.col.f32.bf16.bf16.f32 "                \
        "{%0,%1,%2,%3},{%4,%5,%6,%7},{%8,%9},{%0,%1,%2,%3};"                  \
        : "+f"((C)[0]), "+f"((C)[1]), "+f"((C)[2]), "+f"((C)[3])              \
        : "r"((A)[0]), "r"((A)[1]), "r"((A)[2]), "r"((A)[3]),                 \
          "r"((B)[0]), "r"((B)[1]))

__device__ __forceinline__ void bsplit(float v, unsigned short& h, unsigned short& l) {
    __nv_bfloat16 hb = __float2bfloat16(v);
    __nv_bfloat16 lb = __float2bfloat16(v - __bfloat162float(hb));
    h = __bfloat16_as_ushort(hb);
    l = __bfloat16_as_ushort(lb);
}

// SMEM: A [p][hl] @ p*8192+hl*4096 ; xring @16384 (+3456/slot); h_sm @23296 (+3456/slot)
#define SM_XR 16384
#define SM_HS 23296
#define SM_TOT 30208

// ================= Fused layer body: per-t MMA [h|x]@[Whh|Wih]^T + LSTM cell =========

template<int SRC, int DOLIN>
__device__ __forceinline__ void fused_body(
    const float* __restrict__ xin,
    const float* __restrict__ Wih, const float* __restrict__ Whh,
    const float* __restrict__ bih, const float* __restrict__ bhh,
    const float* __restrict__ h0, const float* __restrict__ c0,
    const float* __restrict__ Wl, const float* __restrict__ bl,
    float* __restrict__ dout, char* sm)
{
    const uint32_t smb = su32(sm);
    unsigned int* h_sm = (unsigned int*)(sm + SM_HS);

    const int tid = threadIdx.x, w = tid >> 5, l = tid & 31;
    const int lq = l >> 2, lr = l & 3, gh = lr & 1;
    const int ntmax = (w == 3) ? 2 : 4;
    const size_t bbase = (size_t)blockIdx.x * RB;

    for (int i = tid; i < 4096; i += 128) ((uint32_t*)sm)[i] = 0;

    // rec B fragments
    uint32_t bfh[4][4][2], bfl[4][4][2];
#pragma unroll
    for (int kb = 0; kb < 4; ++kb)
#pragma unroll
    for (int nt = 0; nt < 4; ++nt)
#pragma unroll
    for (int r = 0; r < 2; ++r) {
        int n = w * 32 + nt * 8 + lq, j = n >> 2, g = n & 3;
        int k0 = kb * 16 + r * 8 + 2 * lr;
        float v0 = 0.f, v1 = 0.f;
        if (j < HH) {
            if (k0 < HH) v0 = Whh[(g * HH + j) * HH + k0];
            else if (k0 < 54) v0 = Wih[(g * HH + j) * HH + k0 - HH];
            int k1 = k0 + 1;
            if (k1 < HH) v1 = Whh[(g * HH + j) * HH + k1];
            else if (k1 < 54) v1 = Wih[(g * HH + j) * HH + k1 - HH];
        }
        unsigned short h0u, l0u, h1u, l1u;
        bsplit(v0, h0u, l0u);
        bsplit(v1, h1u, l1u);
        bfh[kb][nt][r] = ((uint32_t)h1u << 16) | h0u;
        bfl[kb][nt][r] = ((uint32_t)l1u << 16) | l0u;
    }

    // lin B fragments (DOLIN)
    uint32_t wlh[2][2], wll[2][2];
    float2 lbias = make_float2(0.f, 0.f);
    if (DOLIN) {
#pragma unroll
        for (int kb = 0; kb < 2; ++kb)
#pragma unroll
        for (int r = 0; r < 2; ++r) {
            int n = w * 8 + lq;
            int k0 = kb * 16 + r * 8 + 2 * lr;
            float v0 = (n < HH && k0 < HH) ? Wl[n * HH + k0] : 0.f;
            float v1 = (n < HH && k0 + 1 < HH) ? Wl[n * HH + k0 + 1] : 0.f;
            unsigned short h0u, l0u, h1u, l1u;
            bsplit(v0, h0u, l0u);
            bsplit(v1, h1u, l1u);
            wlh[kb][r] = ((uint32_t)h1u << 16) | h0u;
            wll[kb][r] = ((uint32_t)l1u << 16) | l0u;
        }
        int n0 = w * 8 + 2 * lr;
        lbias.x = (n0 < HH) ? bl[n0] : 0.f;
        lbias.y = (n0 + 1 < HH) ? bl[n0 + 1] : 0.f;
    }

    float bias0[4], bias1[4];
#pragma unroll
    for (int nt = 0; nt < 4; ++nt) {
        int jj = w * 8 + 2 * nt + (lr >> 1);
        int g0 = 2 * gh;
        bias0[nt] = (jj < HH) ? bih[g0 * HH + jj] + bhh[g0 * HH + jj] : 0.f;
        bias1[nt] = (jj < HH) ? bih[(g0 + 1) * HH + jj] + bhh[(g0 + 1) * HH + jj] : 0.f;
    }

    float cReg[8];
#pragma unroll
    for (int mt = 0; mt < 2; ++mt)
#pragma unroll
    for (int nt = 0; nt < 4; ++nt) {
        int jj = w * 8 + 2 * nt + (lr >> 1);
        int row = mt * 16 + lq + (gh ? 8 : 0);
        cReg[mt * 4 + nt] = (jj < HH) ? c0[(bbase + row) * HH + jj] : 0.f;
    }

    __syncthreads();

    if (l < HH) {
        for (int rr = 0; rr < 8; ++rr) {
            int row = w * 8 + rr;
            unsigned short hu, lu;
            bsplit(h0[(bbase + row) * HH + l], hu, lu);
            uint32_t a = ((uint32_t)(row * 128 + l * 2)) ^ (uint32_t)((row & 7) << 4);
            ((unsigned short*)sm)[a >> 1] = hu;
            ((unsigned short*)(sm + 4096))[a >> 1] = lu;
        }
    }

    const char* src = SRC ? (const char*)g_hbuf : (const char*)xin;

#pragma unroll
    for (int t0 = 0; t0 < 2; ++t0) {
        if (l < HH) {
            for (int rr = 0; rr < 8; ++rr) {
                int row = w * 8 + rr;
                cpa4(smb + SM_XR + t0 * 3456 + (uint32_t)(row * HH + l) * 4,
                     src + ((bbase + row) * T27 + (size_t)t0 * HH + l) * 4);
            }
        }
        CPC();
    }
    CPW0();
    if (l < HH) {
        for (int rr = 0; rr < 8; ++rr) {
            int row = w * 8 + rr;
            unsigned short hu, lu;
            if (SRC == 0) {
                bsplit(((const float*)(sm + SM_XR))[row * HH + l], hu, lu);
            } else {
                unsigned int u = ((const unsigned int*)(sm + SM_XR))[row * HH + l];
                hu = (unsigned short)(u >> 16);
                lu = (unsigned short)(u & 0xffffu);
            }
            uint32_t a = ((uint32_t)(row * 128 + (HH + l) * 2)) ^ (uint32_t)((row & 7) << 4);
            ((unsigned short*)sm)[a >> 1] = hu;
            ((unsigned short*)(sm + 4096))[a >> 1] = lu;
        }
    }
    __syncthreads();

    int p = 0;
#pragma unroll 1
    for (int t = 0; t < TT; ++t) {
        if (t + 2 < TT && l < HH) {
            for (int rr = 0; rr < 8; ++rr) {
                int row = w * 8 + rr;
                cpa4(smb + SM_XR + (t & 1) * 3456 + (uint32_t)(row * HH + l) * 4,
                     src + ((bbase + row) * T27 + (size_t)(t + 2) * HH + l) * 4);
            }
        }
        CPC();
        CPW1();

        if (t + 1 < TT && l < HH) {
            char* hiB = sm + (p ^ 1) * 8192;
            char* loB = hiB + 4096;
            const char* slot = sm + SM_XR + ((t + 1) & 1) * 3456;
            for (int rr = 0; rr < 8; ++rr) {
                int row = w * 8 + rr;
                unsigned short hu, lu;
                if (SRC == 0) {
                    bsplit(((const float*)slot)[row * HH + l], hu, lu);
                } else {
                    unsigned int u = ((const unsigned int*)slot)[row * HH + l];
                    hu = (unsigned short)(u >> 16);
                    lu = (unsigned short)(u & 0xffffu);
                }
                uint32_t a = ((uint32_t)(row * 128 + (HH + l) * 2)) ^
                             (uint32_t)((row & 7) << 4);
                ((unsigned short*)hiB)[a >> 1] = hu;
                ((unsigned short*)loB)[a >> 1] = lu;
            }
        }

        // division-free flush: warp flushes its 8 rows, lane = column
        if (!DOLIN && t >= 1 && l < HH) {
            const unsigned int* hsrc = h_sm + ((t - 1) & 1) * (RB * HH);
#pragma unroll
            for (int rr = 0; rr < 8; ++rr) {
                int row = w * 8 + rr;
                g_hbuf[(bbase + row) * T27 + (size_t)(t - 1) * HH + l] =
                    hsrc[row * HH + l];
            }
        }

        const uint32_t hiBase = smb + p * 8192;
        const uint32_t loBase = hiBase + 4096;
        char* hiW = sm + (p ^ 1) * 8192;
        char* loW = hiW + 4096;
        unsigned int* hdst = h_sm + (t & 1) * (RB * HH);

#pragma unroll
        for (int mt = 0; mt < 2; ++mt) {
            const int row0 = mt * 16 + lq;
            const uint32_t xr = (uint32_t)((row0 & 7) << 4);
            const uint32_t rb0 = (uint32_t)(row0 * 128);
            const uint32_t rb1 = (uint32_t)((row0 + 8) * 128);
            uint32_t Ah[4][4], Al[2][4];
#pragma unroll
            for (int s = 0; s < 4; ++s) {
                uint32_t cb = (uint32_t)(s * 32 + 4 * lr);
                asm("ld.shared.b32 %0,[%1];" : "=r"(Ah[s][0]) : "r"(hiBase + ((rb0 + cb) ^ xr)));
                asm("ld.shared.b32 %0,[%1];" : "=r"(Ah[s][1]) : "r"(hiBase + ((rb1 + cb) ^ xr)));
                asm("ld.shared.b32 %0,[%1];" : "=r"(Ah[s][2]) : "r"(hiBase + ((rb0 + cb + 16) ^ xr)));
                asm("ld.shared.b32 %0,[%1];" : "=r"(Ah[s][3]) : "r"(hiBase + ((rb1 + cb + 16) ^ xr)));
            }
#pragma unroll
            for (int s = 0; s < 2; ++s) {   // lo-A needed only for h columns (k<32)
                uint32_t cb = (uint32_t)(s * 32 + 4 * lr);
                asm("ld.shared.b32 %0,[%1];" : "=r"(Al[s][0]) : "r"(loBase + ((rb0 + cb) ^ xr)));
                asm("ld.shared.b32 %0,[%1];" : "=r"(Al[s][1]) : "r"(loBase + ((rb1 + cb) ^ xr)));
                asm("ld.shared.b32 %0,[%1];" : "=r"(Al[s][2]) : "r"(loBase + ((rb0 + cb + 16) ^ xr)));
                asm("ld.shared.b32 %0,[%1];" : "=r"(Al[s][3]) : "r"(loBase + ((rb1 + cb + 16) ^ xr)));
            }

            if (DOLIN && t >= 1) {
                float la[4] = {lbias.x, lbias.y, lbias.x, lbias.y};
                float lb2[4] = {0.f, 0.f, 0.f, 0.f};
                MMA(la, Ah[0], wlh[0]);
                MMA(lb2, Ah[0], wll[0]);
                MMA(la, Ah[1], wlh[1]);
                MMA(lb2, Ah[1], wll[1]);
                MMA(lb2, Al[0], wlh[0]);
                MMA(lb2, Al[1], wlh[1]);
                int n0 = w * 8 + 2 * lr;
                float* d0 = dout + (bbase + row0) * (size_t)T27 + (size_t)(t - 1) * HH;
                float* d1 = dout + (bbase + row0 + 8) * (size_t)T27 + (size_t)(t - 1) * HH;
                if (n0 < HH)     { d0[n0] = la[0] + lb2[0];     d1[n0] = la[2] + lb2[2]; }
                if (n0 + 1 < HH) { d0[n0 + 1] = la[1] + lb2[1]; d1[n0 + 1] = la[3] + lb2[3]; }
            }

#pragma unroll
            for (int nt = 0; nt < 4; ++nt) {
                if (nt < ntmax) {
                    float acc[4] = {bias0[nt], bias1[nt], bias0[nt], bias1[nt]};
                    float ac2[4] = {0.f, 0.f, 0.f, 0.f};
#pragma unroll
                    for (int s = 0; s < 4; ++s) {
                        MMA(acc, Ah[s], bfh[s][nt]);
                        MMA(ac2, Ah[s], bfl[s][nt]);
                    }
#pragma unroll
                    for (int s = 0; s < 2; ++s) MMA(ac2, Al[s], bfh[s][nt]);
                    acc[0] += ac2[0];
                    acc[1] += ac2[1];
                    acc[2] += ac2[2];
                    acc[3] += ac2[3];

                    float v0 = __shfl_xor_sync(0xffffffffu, acc[0], 1);
                    float v1 = __shfl_xor_sync(0xffffffffu, acc[1], 1);
                    float v2 = __shfl_xor_sync(0xffffffffu, acc[2], 1);
                    float v3 = __shfl_xor_sync(0xffffffffu, acc[3], 1);
                    int row;
                    float xi, xf, xg, xo;
                    if (gh == 0) { row = row0;     xi = acc[0]; xf = acc[1]; xg = v0; xo = v1; }
                    else         { row = row0 + 8; xi = v2; xf = v3; xg = acc[2]; xo = acc[3]; }
                    float gi = sig_apx(xi), gf = sigf(xf), gg = tapx(xg), go = sig_apx(xo);
                    float cc = fmaf(gf, cReg[mt * 4 + nt], gi * gg);
                    cReg[mt * 4 + nt] = cc;
                    float hv = go * tapx(cc);
                    int jj = w * 8 + 2 * nt + (lr >> 1);
                    if (jj < HH) {
                        unsigned short hu, lu;
                        bsplit(hv, hu, lu);
                        uint32_t a = ((uint32_t)(row * 128 + jj * 2)) ^
                                     (uint32_t)((row & 7) << 4);
                        ((unsigned short*)hiW)[a >> 1] = hu;
                        ((unsigned short*)loW)[a >> 1] = lu;
                        if (!DOLIN) hdst[row * HH + jj] = ((unsigned int)hu << 16) | lu;
                    }
                }
            }
        }
        __syncthreads();
        p ^= 1;
    }

    if (!DOLIN) {
        if (l < HH) {
            const unsigned int* hsrc = h_sm + ((TT - 1) & 1) * (RB * HH);
#pragma unroll
            for (int rr = 0; rr < 8; ++rr) {
                int row = w * 8 + rr;
                g_hbuf[(bbase + row) * T27 + (size_t)(TT - 1) * HH + l] =
                    hsrc[row * HH + l];
            }
        }
    } else {
        const uint32_t hiBase = smb + p * 8192;
        const uint32_t loBase = hiBase + 4096;
#pragma unroll
        for (int mt = 0; mt < 2; ++mt) {
            const int row0 = mt * 16 + lq;
            const uint32_t xr = (uint32_t)((row0 & 7) << 4);
            const uint32_t rb0 = (uint32_t)(row0 * 128);
            const uint32_t rb1 = (uint32_t)((row0 + 8) * 128);
            uint32_t Ah[2][4], Al[2][4];
#pragma unroll
            for (int s = 0; s < 2; ++s) {
                uint32_t cb = (uint32_t)(s * 32 + 4 * lr);
                asm("ld.shared.b32 %0,[%1];" : "=r"(Ah[s][0]) : "r"(hiBase + ((rb0 + cb) ^ xr)));
                asm("ld.shared.b32 %0,[%1];" : "=r"(Ah[s][1]) : "r"(hiBase + ((rb1 + cb) ^ xr)));
                asm("ld.shared.b32 %0,[%1];" : "=r"(Ah[s][2]) : "r"(hiBase + ((rb0 + cb + 16) ^ xr)));
                asm("ld.shared.b32 %0,[%1];" : "=r"(Ah[s][3]) : "r"(hiBase + ((rb1 + cb + 16) ^ xr)));
                asm("ld.shared.b32 %0,[%1];" : "=r"(Al[s][0]) : "r"(loBase + ((rb0 + cb) ^ xr)));
                asm("ld.shared.b32 %0,[%1];" : "=r"(Al[s][1]) : "r"(loBase + ((rb1 + cb) ^ xr)));
                asm("ld.shared.b32 %0,[%1];" : "=r"(Al[s][2]) : "r"(loBase + ((rb0 + cb + 16) ^ xr)));
                asm("ld.shared.b32 %0,[%1];" : "=r"(Al[s][3]) : "r"(loBase + ((rb1 + cb + 16) ^ xr)));
            }
            float la[4] = {lbias.x, lbias.y, lbias.x, lbias.y};
            float lb2[4] = {0.f, 0.f, 0.f, 0.f};
            MMA(la, Ah[0], wlh[0]);
            MMA(lb2, Ah[0], wll[0]);
            MMA(la, Ah[1], wlh[1]);
            MMA(lb2, Ah[1], wll[1]);
            MMA(lb2, Al[0], wlh[0]);
            MMA(lb2, Al[1], wlh[1]);
            int n0 = w * 8 + 2 * lr;
            float* d0 = dout + (bbase + row0) * (size_t)T27 + (size_t)(TT - 1) * HH;
            float* d1 = dout + (bbase + row0 + 8) * (size_t)T27 + (size_t)(TT - 1) * HH;
            if (n0 < HH)     { d0[n0] = la[0] + lb2[0];     d1[n0] = la[2] + lb2[2]; }
            if (n0 + 1 < HH) { d0[n0 + 1] = la[1] + lb2[1]; d1[n0 + 1] = la[3] + lb2[3]; }
        }
    }
}

__global__ void __launch_bounds__(128, 3)
fr_l0(const float* xin, const float* Wih, const float* Whh,
      const float* bih, const float* bhh, const float* h0, const float* c0)
{
    extern __shared__ char sm[];
    fused_body<0, 0>(xin, Wih, Whh, bih, bhh, h0, c0, nullptr, nullptr, nullptr, sm);
}
__global__ void __launch_bounds__(128, 3)
fr_l1(const float* xin, const float* Wih, const float* Whh,
      const float* bih, const float* bhh, const float* h0, const float* c0)
{
    extern __shared__ char sm[];
    fused_body<1, 0>(xin, Wih, Whh, bih, bhh, h0, c0, nullptr, nullptr, nullptr, sm);
}
__global__ void __launch_bounds__(128, 3)
fr_l2(const float* xin, const float* Wih, const float* Whh,
      const float* bih, const float* bhh, const float* h0, const float* c0,
      const float* Wl, const float* bl, float* dout)
{
    extern __shared__ char sm[];
    fused_body<1, 1>(xin, Wih, Whh, bih, bhh, h0, c0, Wl, bl, dout, sm);
}

// ================= host =================
extern "C" void kernel_launch(void* const* d_in, const int* in_sizes, int n_in,
                              void* d_out, int out_size)
{
    const float* x   = (const float*)d_in[0];
    const float* h0  = (const float*)d_in[1];
    const float* c0  = (const float*)d_in[2];
    const float* Wih = (const float*)d_in[3];
    const float* Whh = (const float*)d_in[4];
    const float* bih = (const float*)d_in[5];
    const float* bhh = (const float*)d_in[6];
    const float* Wl  = (const float*)d_in[7];
    const float* bl  = (const float*)d_in[8];
    float* out = (float*)d_out;

    const size_t st = (size_t)BB * HH;
    const size_t wS = (size_t)GG * HH;
    const size_t bS = (size_t)GG;

    cudaFuncSetAttribute(fr_l0, cudaFuncAttributeMaxDynamicSharedMemorySize, SM_TOT);
    cudaFuncSetAttribute(fr_l1, cudaFuncAttributeMaxDynamicSharedMemorySize, SM_TOT);
    cudaFuncSetAttribute(fr_l2, cudaFuncAttributeMaxDynamicSharedMemorySize, SM_TOT);

    const int grid = BB / RB;   // 1024

    fr_l0<<<grid, 128, SM_TOT>>>(x, Wih, Whh, bih, bhh, h0, c0);
    fr_l1<<<grid, 128, SM_TOT>>>(x, Wih + wS, Whh + wS, bih + bS, bhh + bS,
                                 h0 + st, c0 + st);
    fr_l2<<<grid, 128, SM_TOT>>>(x, Wih + 2 * wS, Whh + 2 * wS,
                                 bih + 2 * bS, bhh + 2 * bS,
                                 h0 + 2 * st, c0 + 2 * st, Wl, bl, out);
}